// round 1
// baseline (speedup 1.0000x reference)
#include <cuda_runtime.h>
#include <cuda_bf16.h>
#include <math.h>

// Problem constants (fixed shapes)
#define BB 4
#define TT 4096
#define DD 1024
#define SPAN 128
#define NB (TT / SPAN)      // 32
#define MROWS (BB * TT)     // 16384

// Scratch for q, k, v projections (device globals: no allocation APIs allowed)
__device__ float g_q[(size_t)MROWS * DD];
__device__ float g_k[(size_t)MROWS * DD];
__device__ float g_v[(size_t)MROWS * DD];

// ---------------------------------------------------------------------------
// QKV projection GEMM:  C[m, n] = sum_d A[m, d] * W[n, d] + bias[n]
// A: [16384, 1024] row-major, W: [1024, 1024] row-major (both read along d).
// Block tile 128x128, K-chunk 16, 256 threads, 8x8 per thread.
// ---------------------------------------------------------------------------
__global__ __launch_bounds__(256) void qkv_gemm(const float* __restrict__ A,
                                                const float* __restrict__ W,
                                                const float* __restrict__ bias,
                                                float* __restrict__ C) {
    __shared__ float As[16][128];
    __shared__ float Ws[16][128];

    const int bm = blockIdx.y * 128;
    const int bn = blockIdx.x * 128;
    const int tid = threadIdx.x;
    const int tr = (tid / 16) * 8;   // output row base within tile
    const int tc = (tid % 16) * 8;   // output col base within tile

    float acc[8][8];
#pragma unroll
    for (int i = 0; i < 8; i++)
#pragma unroll
        for (int j = 0; j < 8; j++) acc[i][j] = 0.0f;

    for (int k0 = 0; k0 < DD; k0 += 16) {
        // Load A tile (128 rows x 16 cols) and W tile, transposed into smem.
        // 512 float4 per tile, 2 per thread.
#pragma unroll
        for (int h = 0; h < 2; h++) {
            int idx = tid + h * 256;          // 0..511
            int r   = idx >> 2;               // 0..127
            int c   = (idx & 3) * 4;          // 0,4,8,12
            float4 av = *(const float4*)(A + (size_t)(bm + r) * DD + k0 + c);
            As[c + 0][r] = av.x; As[c + 1][r] = av.y;
            As[c + 2][r] = av.z; As[c + 3][r] = av.w;
            float4 wv = *(const float4*)(W + (size_t)(bn + r) * DD + k0 + c);
            Ws[c + 0][r] = wv.x; Ws[c + 1][r] = wv.y;
            Ws[c + 2][r] = wv.z; Ws[c + 3][r] = wv.w;
        }
        __syncthreads();

#pragma unroll
        for (int k = 0; k < 16; k++) {
            float a[8], w[8];
#pragma unroll
            for (int i = 0; i < 8; i++) a[i] = As[k][tr + i];
#pragma unroll
            for (int j = 0; j < 8; j++) w[j] = Ws[k][tc + j];
#pragma unroll
            for (int i = 0; i < 8; i++)
#pragma unroll
                for (int j = 0; j < 8; j++) acc[i][j] += a[i] * w[j];
        }
        __syncthreads();
    }

    // Epilogue: add bias, store
#pragma unroll
    for (int i = 0; i < 8; i++) {
#pragma unroll
        for (int j = 0; j < 8; j += 4) {
            float4 o;
            o.x = acc[i][j + 0] + bias[bn + tc + j + 0];
            o.y = acc[i][j + 1] + bias[bn + tc + j + 1];
            o.z = acc[i][j + 2] + bias[bn + tc + j + 2];
            o.w = acc[i][j + 3] + bias[bn + tc + j + 3];
            *(float4*)(C + (size_t)(bm + tr + i) * DD + bn + tc + j) = o;
        }
    }
}

// ---------------------------------------------------------------------------
// Windowed attention. One CTA per (batch b, query block n). Query block of
// 128 rows attends to keys [prev block | current block] (256 keys) with
// mask: k in (q, q+128], and for n==0 additionally k >= 128 (padding).
// Phase 1: S[128][256] = Q_blk @ K_win^T  (accumulated over D in chunks of 16)
// Phase 2: masked softmax (scale 1/32) in smem
// Phase 3: O_blk = P @ V_win  (V streamed through smem in 32-row chunks)
// 512 threads. Dynamic smem: S (128KB) + Q chunk (8KB) + K/V chunk (16KB).
// ---------------------------------------------------------------------------
#define ATTN_SMEM_FLOATS (128 * 256 + 16 * 128 + 16 * 256)

__global__ __launch_bounds__(512) void attn_kernel(const float* __restrict__ Q,
                                                   const float* __restrict__ K,
                                                   const float* __restrict__ V,
                                                   float* __restrict__ O) {
    extern __shared__ float sm[];
    float* Ssc = sm;                        // [128][256]
    float* Qs  = sm + 128 * 256;            // [16][128]
    float* KVs = Qs + 16 * 128;             // [16][256] in phase 1, [32][128] in phase 3

    const int n = blockIdx.x;               // query block 0..31
    const int b = blockIdx.y;               // batch 0..3
    const int tid = threadIdx.x;
    const size_t qbase = ((size_t)b * TT + (size_t)n * SPAN) * DD;  // first q row * D
    const int kv0 = (n - 1) * SPAN;         // first key row within batch (may be -128)

    // ---------------- Phase 1: scores ----------------
    {
        const int tr = (tid >> 5) * 8;      // q rows (16 groups of 8)
        const int tc = (tid & 31) * 8;      // k cols (32 groups of 8)
        float acc[8][8];
#pragma unroll
        for (int i = 0; i < 8; i++)
#pragma unroll
            for (int j = 0; j < 8; j++) acc[i][j] = 0.0f;

        for (int d0 = 0; d0 < DD; d0 += 16) {
            // Q chunk: 128 rows x 16 d -> 512 float4, one per thread
            {
                int r = tid >> 2;
                int c = (tid & 3) * 4;
                float4 qv = *(const float4*)(Q + qbase + (size_t)r * DD + d0 + c);
                Qs[(c + 0) * 128 + r] = qv.x; Qs[(c + 1) * 128 + r] = qv.y;
                Qs[(c + 2) * 128 + r] = qv.z; Qs[(c + 3) * 128 + r] = qv.w;
            }
            // K chunk: 256 rows x 16 d -> 1024 float4, two per thread
#pragma unroll
            for (int h = 0; h < 2; h++) {
                int idx = tid + h * 512;
                int kr  = idx >> 2;         // 0..255
                int c   = (idx & 3) * 4;
                int krow = kv0 + kr;
                if (krow < 0) krow = 0;     // masked later; just avoid OOB
                float4 kv = *(const float4*)(K + ((size_t)b * TT + krow) * DD + d0 + c);
                KVs[(c + 0) * 256 + kr] = kv.x; KVs[(c + 1) * 256 + kr] = kv.y;
                KVs[(c + 2) * 256 + kr] = kv.z; KVs[(c + 3) * 256 + kr] = kv.w;
            }
            __syncthreads();

#pragma unroll
            for (int k = 0; k < 16; k++) {
                float a[8], w[8];
#pragma unroll
                for (int i = 0; i < 8; i++) a[i] = Qs[k * 128 + tr + i];
#pragma unroll
                for (int j = 0; j < 8; j++) w[j] = KVs[k * 256 + tc + j];
#pragma unroll
                for (int i = 0; i < 8; i++)
#pragma unroll
                    for (int j = 0; j < 8; j++) acc[i][j] += a[i] * w[j];
            }
            __syncthreads();
        }

        // Write scores to smem
#pragma unroll
        for (int i = 0; i < 8; i++) {
#pragma unroll
            for (int j = 0; j < 8; j += 4) {
                float4 o;
                o.x = acc[i][j + 0]; o.y = acc[i][j + 1];
                o.z = acc[i][j + 2]; o.w = acc[i][j + 3];
                *(float4*)&Ssc[(tr + i) * 256 + tc + j] = o;
            }
        }
        __syncthreads();
    }

    // ---------------- Phase 2: masked softmax ----------------
    {
        const int wid = tid >> 5;
        const int lane = tid & 31;
        const float scale = 0.03125f;  // 1/sqrt(1024)
#pragma unroll
        for (int rr = 0; rr < 8; rr++) {
            int row = wid * 8 + rr;    // query offset within block
            float sv[8];
            bool ok[8];
            float m = -INFINITY;
#pragma unroll
            for (int u = 0; u < 8; u++) {
                int kk = lane + u * 32;
                float s = Ssc[row * 256 + kk] * scale;
                // window: k in (row, row+128]; first block: prev half is padding
                bool v = (kk > row) && (kk <= row + SPAN) && (n > 0 || kk >= SPAN);
                sv[u] = s; ok[u] = v;
                if (v) m = fmaxf(m, s);
            }
#pragma unroll
            for (int o = 16; o > 0; o >>= 1) m = fmaxf(m, __shfl_xor_sync(0xFFFFFFFFu, m, o));
            float p[8];
            float sum = 0.0f;
#pragma unroll
            for (int u = 0; u < 8; u++) {
                p[u] = ok[u] ? __expf(sv[u] - m) : 0.0f;
                sum += p[u];
            }
#pragma unroll
            for (int o = 16; o > 0; o >>= 1) sum += __shfl_xor_sync(0xFFFFFFFFu, sum, o);
            float inv = 1.0f / sum;
#pragma unroll
            for (int u = 0; u < 8; u++) Ssc[row * 256 + lane + u * 32] = p[u] * inv;
        }
        __syncthreads();
    }

    // ---------------- Phase 3: O = P @ V ----------------
    {
        const int wid = tid >> 5;
        const int lane = tid & 31;
        const int qr = wid * 8;        // 8 query rows per warp

        for (int d0 = 0; d0 < DD; d0 += 128) {
            float acc[8][4];
#pragma unroll
            for (int i = 0; i < 8; i++)
#pragma unroll
                for (int j = 0; j < 4; j++) acc[i][j] = 0.0f;

            for (int k0 = 0; k0 < 256; k0 += 32) {
                // Load V chunk: 32 key rows x 128 d -> 1024 float4, two per thread
#pragma unroll
                for (int h = 0; h < 2; h++) {
                    int idx = tid + h * 512;
                    int vr  = idx >> 5;            // 0..31
                    int vc  = (idx & 31) * 4;      // 0..124
                    int vrow = kv0 + k0 + vr;
                    if (vrow < 0) vrow = 0;        // P is 0 there
                    float4 vv = *(const float4*)(V + ((size_t)b * TT + vrow) * DD + d0 + vc);
                    *(float4*)&KVs[vr * 128 + vc] = vv;
                }
                __syncthreads();

#pragma unroll
                for (int k = 0; k < 32; k++) {
                    float4 v4 = *(const float4*)&KVs[k * 128 + lane * 4];
#pragma unroll
                    for (int i = 0; i < 8; i++) {
                        float p = Ssc[(qr + i) * 256 + k0 + k];  // warp-broadcast
                        acc[i][0] += p * v4.x; acc[i][1] += p * v4.y;
                        acc[i][2] += p * v4.z; acc[i][3] += p * v4.w;
                    }
                }
                __syncthreads();
            }

#pragma unroll
            for (int i = 0; i < 8; i++) {
                float4 o;
                o.x = acc[i][0]; o.y = acc[i][1]; o.z = acc[i][2]; o.w = acc[i][3];
                *(float4*)(O + qbase + (size_t)(qr + i) * DD + d0 + lane * 4) = o;
            }
        }
    }
}

// ---------------------------------------------------------------------------
extern "C" void kernel_launch(void* const* d_in, const int* in_sizes, int n_in,
                              void* d_out, int out_size) {
    const float* x  = (const float*)d_in[0];
    const float* Wq = (const float*)d_in[1];
    const float* bq = (const float*)d_in[2];
    const float* Wk = (const float*)d_in[3];
    const float* bk = (const float*)d_in[4];
    const float* Wv = (const float*)d_in[5];
    const float* bv = (const float*)d_in[6];
    float* out = (float*)d_out;

    float *q, *k, *v;
    cudaGetSymbolAddress((void**)&q, g_q);
    cudaGetSymbolAddress((void**)&k, g_k);
    cudaGetSymbolAddress((void**)&v, g_v);

    dim3 ggrid(DD / 128, MROWS / 128);   // (8, 128)
    qkv_gemm<<<ggrid, 256>>>(x, Wq, bq, q);
    qkv_gemm<<<ggrid, 256>>>(x, Wk, bk, k);
    qkv_gemm<<<ggrid, 256>>>(x, Wv, bv, v);

    size_t smem_bytes = (size_t)ATTN_SMEM_FLOATS * sizeof(float);  // ~152 KB
    cudaFuncSetAttribute(attn_kernel, cudaFuncAttributeMaxDynamicSharedMemorySize,
                         (int)smem_bytes);
    attn_kernel<<<dim3(NB, BB), 512, smem_bytes>>>(q, k, v, out);
}

// round 5
// speedup vs baseline: 2.2950x; 2.2950x over previous
#include <cuda_runtime.h>
#include <cuda_bf16.h>
#include <math.h>
#include <stdint.h>

// Problem constants (fixed shapes)
#define BB 4
#define TT 4096
#define DD 1024
#define SPAN 128
#define NB (TT / SPAN)      // 32
#define MROWS (BB * TT)     // 16384

// Scratch (device globals: no allocation APIs allowed)
__device__ float g_q[(size_t)MROWS * DD];
__device__ float g_k[(size_t)MROWS * DD];
__device__ float g_v[(size_t)MROWS * DD];
__device__ __nv_bfloat16 g_xh[(size_t)MROWS * DD];
__device__ __nv_bfloat16 g_xl[(size_t)MROWS * DD];
__device__ __nv_bfloat16 g_wh[(size_t)3 * DD * DD];
__device__ __nv_bfloat16 g_wl[(size_t)3 * DD * DD];

__device__ __forceinline__ uint32_t smem_u32(const void* p) {
    uint32_t a;
    asm("{ .reg .u64 t; cvta.to.shared.u64 t, %1; cvt.u32.u64 %0, t; }"
        : "=r"(a) : "l"(p));
    return a;
}

#define LDMATRIX_X4(r0, r1, r2, r3, addr) \
    asm volatile("ldmatrix.sync.aligned.m8n8.x4.shared.b16 {%0,%1,%2,%3}, [%4];" \
                 : "=r"(r0), "=r"(r1), "=r"(r2), "=r"(r3) : "r"(addr))
#define LDMATRIX_X2(r0, r1, addr) \
    asm volatile("ldmatrix.sync.aligned.m8n8.x2.shared.b16 {%0,%1}, [%2];" \
                 : "=r"(r0), "=r"(r1) : "r"(addr))
#define MMA_16816(c0, c1, c2, c3, a0, a1, a2, a3, b0, b1) \
    asm volatile("mma.sync.aligned.m16n8k16.row.col.f32.bf16.bf16.f32 " \
                 "{%0,%1,%2,%3}, {%4,%5,%6,%7}, {%8,%9}, {%0,%1,%2,%3};" \
                 : "+f"(c0), "+f"(c1), "+f"(c2), "+f"(c3) \
                 : "r"(a0), "r"(a1), "r"(a2), "r"(a3), "r"(b0), "r"(b1))
#define CP_ASYNC_16(dst, src) \
    asm volatile("cp.async.cg.shared.global [%0], [%1], 16;" \
                 :: "r"(dst), "l"(src) : "memory")
#define CP_ASYNC_COMMIT() asm volatile("cp.async.commit_group;" ::: "memory")
#define CP_ASYNC_WAIT(n)  asm volatile("cp.async.wait_group %0;" :: "n"(n) : "memory")

// ---------------------------------------------------------------------------
// Split fp32 -> bf16 hi + bf16 lo   (A ~= hi + lo, each term exactly bf16)
// ---------------------------------------------------------------------------
__global__ __launch_bounds__(256) void split_bf16(const float* __restrict__ src,
                                                  __nv_bfloat16* __restrict__ hi,
                                                  __nv_bfloat16* __restrict__ lo,
                                                  int n4) {
    int i = blockIdx.x * 256 + threadIdx.x;
    if (i >= n4) return;
    float4 v = reinterpret_cast<const float4*>(src)[i];
    __nv_bfloat16 h0 = __float2bfloat16(v.x);
    __nv_bfloat16 h1 = __float2bfloat16(v.y);
    __nv_bfloat16 h2 = __float2bfloat16(v.z);
    __nv_bfloat16 h3 = __float2bfloat16(v.w);
    __nv_bfloat16 l0 = __float2bfloat16(v.x - __bfloat162float(h0));
    __nv_bfloat16 l1 = __float2bfloat16(v.y - __bfloat162float(h1));
    __nv_bfloat16 l2 = __float2bfloat16(v.z - __bfloat162float(h2));
    __nv_bfloat16 l3 = __float2bfloat16(v.w - __bfloat162float(h3));
    ushort4 hv, lv;
    hv.x = __bfloat16_as_ushort(h0); hv.y = __bfloat16_as_ushort(h1);
    hv.z = __bfloat16_as_ushort(h2); hv.w = __bfloat16_as_ushort(h3);
    lv.x = __bfloat16_as_ushort(l0); lv.y = __bfloat16_as_ushort(l1);
    lv.z = __bfloat16_as_ushort(l2); lv.w = __bfloat16_as_ushort(l3);
    reinterpret_cast<ushort4*>(hi)[i] = hv;
    reinterpret_cast<ushort4*>(lo)[i] = lv;
}

// ---------------------------------------------------------------------------
// Split-bf16 tensor-core GEMM via ldmatrix + mma.sync (sm_80 ISA, runs on the
// Blackwell HMMA fallback pipe):  out[m,n] = sum_d A[m,d] * W[n,d] + bias[n]
// C = Ah@Wh + Ah@Wl + Al@Wh (fp32 accum in registers)
// CTA tile M=128, N=128, K-chunk 64 (128B rows, SW128 swizzle).
// 256 threads = 8 warps (2x4), warp tile 64x32. cp.async double buffer.
// ---------------------------------------------------------------------------
struct GemmArgs {
    const __nv_bfloat16* xh;
    const __nv_bfloat16* xl;
    const __nv_bfloat16* wh[3];
    const __nv_bfloat16* wl[3];
    const float* bias[3];
    float* out[3];
};

#define TILE_BYTES 16384u        // 128 rows x 128B (64 bf16)
#define STAGE_BYTES (4u * TILE_BYTES)
#define NUM_CHUNKS (DD / 64)     // 16
#define GEMM_DSMEM (2u * STAGE_BYTES)

__global__ __launch_bounds__(256) void qkv_tc_gemm(GemmArgs args) {
    extern __shared__ char dsm[];
    const int tid = threadIdx.x;
    const int wid = tid >> 5;
    const int lane = tid & 31;
    const int bn = blockIdx.x * 128;
    const int bm = blockIdx.y * 128;
    const int z  = blockIdx.z;
    const int warp_m = wid >> 2;     // 0..1 -> rows 64*warp_m
    const int warp_n = wid & 3;      // 0..3 -> cols 32*warp_n

    const uint32_t smem_base = smem_u32(dsm);

    const __nv_bfloat16* srcs[4] = {
        args.xh    + (size_t)bm * DD,
        args.xl    + (size_t)bm * DD,
        args.wh[z] + (size_t)bn * DD,
        args.wl[z] + (size_t)bn * DD };

    // per-thread cp.async mapping: 4 ld/tile, idx = tid + i*256
    // row = idx>>3 (0..127), ch = idx&7 (16B chunk)
    // dst = row*128 + ((ch ^ (row&7))*16)
    uint32_t ld_dst[4];
    uint32_t ld_row[4], ld_ch[4];
#pragma unroll
    for (int i = 0; i < 4; ++i) {
        int idx = tid + i * 256;
        int r = idx >> 3, ch = idx & 7;
        ld_row[i] = r; ld_ch[i] = ch;
        ld_dst[i] = (uint32_t)(r * 128 + ((ch ^ (r & 7)) * 16));
    }

    auto load_stage = [&](int c, int buf) {
        const int k0 = c * 64;
        const uint32_t sb = smem_base + buf * STAGE_BYTES;
#pragma unroll
        for (int t = 0; t < 4; ++t) {
            const __nv_bfloat16* p = srcs[t] + k0;
            const uint32_t tb = sb + t * TILE_BYTES;
#pragma unroll
            for (int i = 0; i < 4; ++i) {
                const __nv_bfloat16* src = p + (size_t)ld_row[i] * DD + ld_ch[i] * 8;
                CP_ASYNC_16(tb + ld_dst[i], src);
            }
        }
        CP_ASYNC_COMMIT();
    };

    float acc[4][4][4];
#pragma unroll
    for (int mt = 0; mt < 4; ++mt)
#pragma unroll
        for (int nt = 0; nt < 4; ++nt)
#pragma unroll
            for (int j = 0; j < 4; ++j) acc[mt][nt][j] = 0.0f;

    // ldmatrix per-thread address components
    // A (x4): row = warpm*64 + mt*16 + (lane&15), kb = kstep*32 + (lane>>4)*16
    const int a_row = warp_m * 64 + (lane & 15);
    const uint32_t a_sw = (uint32_t)((a_row & 7) * 16);
    const uint32_t a_kb_lane = (uint32_t)((lane >> 4) * 16);
    // B (x2): row = warpn*32 + nt*8 + (lane&7), kb = kstep*32 + ((lane>>3)&1)*16
    const int b_row = warp_n * 32 + (lane & 7);
    const uint32_t b_sw = (uint32_t)((b_row & 7) * 16);
    const uint32_t b_kb_lane = (uint32_t)(((lane >> 3) & 1) * 16);

    load_stage(0, 0);

    for (int c = 0; c < NUM_CHUNKS; ++c) {
        const int buf = c & 1;
        if (c + 1 < NUM_CHUNKS) {
            load_stage(c + 1, (c + 1) & 1);
            CP_ASYNC_WAIT(1);
        } else {
            CP_ASYNC_WAIT(0);
        }
        __syncthreads();

        const uint32_t sb = smem_base + buf * STAGE_BYTES;
        const uint32_t a_base_h = sb + 0 * TILE_BYTES + a_row * 128;
        const uint32_t a_base_l = sb + 1 * TILE_BYTES + a_row * 128;
        const uint32_t b_base_h = sb + 2 * TILE_BYTES + b_row * 128;
        const uint32_t b_base_l = sb + 3 * TILE_BYTES + b_row * 128;

#pragma unroll
        for (int ks = 0; ks < 4; ++ks) {
            const uint32_t akb = (uint32_t)(ks * 32) + a_kb_lane;
            const uint32_t bkb = (uint32_t)(ks * 32) + b_kb_lane;
            uint32_t ah[4][4], al[4][4];
#pragma unroll
            for (int mt = 0; mt < 4; ++mt) {
                const uint32_t moff = (uint32_t)(mt * 16 * 128);
                LDMATRIX_X4(ah[mt][0], ah[mt][1], ah[mt][2], ah[mt][3],
                            a_base_h + moff + (akb ^ a_sw));
                LDMATRIX_X4(al[mt][0], al[mt][1], al[mt][2], al[mt][3],
                            a_base_l + moff + (akb ^ a_sw));
            }
            uint32_t bh[4][2], bl[4][2];
#pragma unroll
            for (int nt = 0; nt < 4; ++nt) {
                const uint32_t noff = (uint32_t)(nt * 8 * 128);
                LDMATRIX_X2(bh[nt][0], bh[nt][1], b_base_h + noff + (bkb ^ b_sw));
                LDMATRIX_X2(bl[nt][0], bl[nt][1], b_base_l + noff + (bkb ^ b_sw));
            }
#pragma unroll
            for (int mt = 0; mt < 4; ++mt) {
#pragma unroll
                for (int nt = 0; nt < 4; ++nt) {
                    MMA_16816(acc[mt][nt][0], acc[mt][nt][1], acc[mt][nt][2], acc[mt][nt][3],
                              ah[mt][0], ah[mt][1], ah[mt][2], ah[mt][3],
                              bh[nt][0], bh[nt][1]);
                    MMA_16816(acc[mt][nt][0], acc[mt][nt][1], acc[mt][nt][2], acc[mt][nt][3],
                              ah[mt][0], ah[mt][1], ah[mt][2], ah[mt][3],
                              bl[nt][0], bl[nt][1]);
                    MMA_16816(acc[mt][nt][0], acc[mt][nt][1], acc[mt][nt][2], acc[mt][nt][3],
                              al[mt][0], al[mt][1], al[mt][2], al[mt][3],
                              bh[nt][0], bh[nt][1]);
                }
            }
        }
        __syncthreads();
    }

    // Epilogue: c0,c1 at (row, col..col+1); c2,c3 at (row+8, ...)
    const float* bias = args.bias[z];
    float* out = args.out[z];
    const int er = bm + warp_m * 64 + (lane >> 2);
    const int ec = bn + warp_n * 32 + (lane & 3) * 2;
#pragma unroll
    for (int mt = 0; mt < 4; ++mt) {
#pragma unroll
        for (int nt = 0; nt < 4; ++nt) {
            const int r0 = er + mt * 16;
            const int cc = ec + nt * 8;
            float2 v0, v1;
            v0.x = acc[mt][nt][0] + bias[cc];
            v0.y = acc[mt][nt][1] + bias[cc + 1];
            v1.x = acc[mt][nt][2] + bias[cc];
            v1.y = acc[mt][nt][3] + bias[cc + 1];
            *reinterpret_cast<float2*>(out + (size_t)r0 * DD + cc) = v0;
            *reinterpret_cast<float2*>(out + (size_t)(r0 + 8) * DD + cc) = v1;
        }
    }
}

// ---------------------------------------------------------------------------
// Windowed attention (unchanged from R1 baseline): one CTA per (b, n).
// ---------------------------------------------------------------------------
#define ATTN_SMEM_FLOATS (128 * 256 + 16 * 128 + 16 * 256)

__global__ __launch_bounds__(512) void attn_kernel(const float* __restrict__ Q,
                                                   const float* __restrict__ K,
                                                   const float* __restrict__ V,
                                                   float* __restrict__ O) {
    extern __shared__ float sm[];
    float* Ssc = sm;                        // [128][256]
    float* Qs  = sm + 128 * 256;            // [16][128]
    float* KVs = Qs + 16 * 128;             // [16][256] phase 1, [32][128] phase 3

    const int n = blockIdx.x;
    const int b = blockIdx.y;
    const int tid = threadIdx.x;
    const size_t qbase = ((size_t)b * TT + (size_t)n * SPAN) * DD;
    const int kv0 = (n - 1) * SPAN;

    // ---------------- Phase 1: scores ----------------
    {
        const int tr = (tid >> 5) * 8;
        const int tc = (tid & 31) * 8;
        float acc[8][8];
#pragma unroll
        for (int i = 0; i < 8; i++)
#pragma unroll
            for (int j = 0; j < 8; j++) acc[i][j] = 0.0f;

        for (int d0 = 0; d0 < DD; d0 += 16) {
            {
                int r = tid >> 2;
                int c = (tid & 3) * 4;
                float4 qv = *(const float4*)(Q + qbase + (size_t)r * DD + d0 + c);
                Qs[(c + 0) * 128 + r] = qv.x; Qs[(c + 1) * 128 + r] = qv.y;
                Qs[(c + 2) * 128 + r] = qv.z; Qs[(c + 3) * 128 + r] = qv.w;
            }
#pragma unroll
            for (int h = 0; h < 2; h++) {
                int idx = tid + h * 512;
                int kr  = idx >> 2;
                int c   = (idx & 3) * 4;
                int krow = kv0 + kr;
                if (krow < 0) krow = 0;
                float4 kv = *(const float4*)(K + ((size_t)b * TT + krow) * DD + d0 + c);
                KVs[(c + 0) * 256 + kr] = kv.x; KVs[(c + 1) * 256 + kr] = kv.y;
                KVs[(c + 2) * 256 + kr] = kv.z; KVs[(c + 3) * 256 + kr] = kv.w;
            }
            __syncthreads();

#pragma unroll
            for (int k = 0; k < 16; k++) {
                float a[8], w[8];
#pragma unroll
                for (int i = 0; i < 8; i++) a[i] = Qs[k * 128 + tr + i];
#pragma unroll
                for (int j = 0; j < 8; j++) w[j] = KVs[k * 256 + tc + j];
#pragma unroll
                for (int i = 0; i < 8; i++)
#pragma unroll
                    for (int j = 0; j < 8; j++) acc[i][j] += a[i] * w[j];
            }
            __syncthreads();
        }

#pragma unroll
        for (int i = 0; i < 8; i++) {
#pragma unroll
            for (int j = 0; j < 8; j += 4) {
                float4 o;
                o.x = acc[i][j + 0]; o.y = acc[i][j + 1];
                o.z = acc[i][j + 2]; o.w = acc[i][j + 3];
                *(float4*)&Ssc[(tr + i) * 256 + tc + j] = o;
            }
        }
        __syncthreads();
    }

    // ---------------- Phase 2: masked softmax ----------------
    {
        const int wid = tid >> 5;
        const int lane = tid & 31;
        const float scale = 0.03125f;
#pragma unroll
        for (int rr = 0; rr < 8; rr++) {
            int row = wid * 8 + rr;
            float sv[8];
            bool ok[8];
            float m = -INFINITY;
#pragma unroll
            for (int u = 0; u < 8; u++) {
                int kk = lane + u * 32;
                float s = Ssc[row * 256 + kk] * scale;
                bool v = (kk > row) && (kk <= row + SPAN) && (n > 0 || kk >= SPAN);
                sv[u] = s; ok[u] = v;
                if (v) m = fmaxf(m, s);
            }
#pragma unroll
            for (int o = 16; o > 0; o >>= 1) m = fmaxf(m, __shfl_xor_sync(0xFFFFFFFFu, m, o));
            float p[8];
            float sum = 0.0f;
#pragma unroll
            for (int u = 0; u < 8; u++) {
                p[u] = ok[u] ? __expf(sv[u] - m) : 0.0f;
                sum += p[u];
            }
#pragma unroll
            for (int o = 16; o > 0; o >>= 1) sum += __shfl_xor_sync(0xFFFFFFFFu, sum, o);
            float inv = 1.0f / sum;
#pragma unroll
            for (int u = 0; u < 8; u++) Ssc[row * 256 + lane + u * 32] = p[u] * inv;
        }
        __syncthreads();
    }

    // ---------------- Phase 3: O = P @ V ----------------
    {
        const int wid = tid >> 5;
        const int lane = tid & 31;
        const int qr = wid * 8;

        for (int d0 = 0; d0 < DD; d0 += 128) {
            float acc[8][4];
#pragma unroll
            for (int i = 0; i < 8; i++)
#pragma unroll
                for (int j = 0; j < 4; j++) acc[i][j] = 0.0f;

            for (int k0 = 0; k0 < 256; k0 += 32) {
#pragma unroll
                for (int h = 0; h < 2; h++) {
                    int idx = tid + h * 512;
                    int vr  = idx >> 5;
                    int vc  = (idx & 31) * 4;
                    int vrow = kv0 + k0 + vr;
                    if (vrow < 0) vrow = 0;
                    float4 vv = *(const float4*)(V + ((size_t)b * TT + vrow) * DD + d0 + vc);
                    *(float4*)&KVs[vr * 128 + vc] = vv;
                }
                __syncthreads();

#pragma unroll
                for (int k = 0; k < 32; k++) {
                    float4 v4 = *(const float4*)&KVs[k * 128 + lane * 4];
#pragma unroll
                    for (int i = 0; i < 8; i++) {
                        float p = Ssc[(qr + i) * 256 + k0 + k];
                        acc[i][0] += p * v4.x; acc[i][1] += p * v4.y;
                        acc[i][2] += p * v4.z; acc[i][3] += p * v4.w;
                    }
                }
                __syncthreads();
            }

#pragma unroll
            for (int i = 0; i < 8; i++) {
                float4 o;
                o.x = acc[i][0]; o.y = acc[i][1]; o.z = acc[i][2]; o.w = acc[i][3];
                *(float4*)(O + qbase + (size_t)(qr + i) * DD + d0 + lane * 4) = o;
            }
        }
    }
}

// ---------------------------------------------------------------------------
extern "C" void kernel_launch(void* const* d_in, const int* in_sizes, int n_in,
                              void* d_out, int out_size) {
    const float* x  = (const float*)d_in[0];
    const float* Wq = (const float*)d_in[1];
    const float* bq = (const float*)d_in[2];
    const float* Wk = (const float*)d_in[3];
    const float* bk = (const float*)d_in[4];
    const float* Wv = (const float*)d_in[5];
    const float* bv = (const float*)d_in[6];
    float* out = (float*)d_out;

    float *q, *k, *v;
    cudaGetSymbolAddress((void**)&q, g_q);
    cudaGetSymbolAddress((void**)&k, g_k);
    cudaGetSymbolAddress((void**)&v, g_v);
    __nv_bfloat16 *xh, *xl, *wh, *wl;
    cudaGetSymbolAddress((void**)&xh, g_xh);
    cudaGetSymbolAddress((void**)&xl, g_xl);
    cudaGetSymbolAddress((void**)&wh, g_wh);
    cudaGetSymbolAddress((void**)&wl, g_wl);

    // Split fp32 -> bf16 hi/lo
    {
        int n4 = MROWS * DD / 4;
        split_bf16<<<(n4 + 255) / 256, 256>>>(x, xh, xl, n4);
        int w4 = DD * DD / 4;
        split_bf16<<<(w4 + 255) / 256, 256>>>(Wq, wh + 0 * DD * DD, wl + 0 * DD * DD, w4);
        split_bf16<<<(w4 + 255) / 256, 256>>>(Wk, wh + 1 * DD * DD, wl + 1 * DD * DD, w4);
        split_bf16<<<(w4 + 255) / 256, 256>>>(Wv, wh + 2 * DD * DD, wl + 2 * DD * DD, w4);
    }

    GemmArgs ga;
    ga.xh = xh; ga.xl = xl;
    ga.wh[0] = wh;               ga.wl[0] = wl;
    ga.wh[1] = wh + 1 * DD * DD; ga.wl[1] = wl + 1 * DD * DD;
    ga.wh[2] = wh + 2 * DD * DD; ga.wl[2] = wl + 2 * DD * DD;
    ga.bias[0] = bq; ga.bias[1] = bk; ga.bias[2] = bv;
    ga.out[0]  = q;  ga.out[1]  = k;  ga.out[2]  = v;

    cudaFuncSetAttribute(qkv_tc_gemm, cudaFuncAttributeMaxDynamicSharedMemorySize,
                         GEMM_DSMEM);
    qkv_tc_gemm<<<dim3(DD / 128, MROWS / 128, 3), 256, GEMM_DSMEM>>>(ga);

    size_t smem_bytes = (size_t)ATTN_SMEM_FLOATS * sizeof(float);
    cudaFuncSetAttribute(attn_kernel, cudaFuncAttributeMaxDynamicSharedMemorySize,
                         (int)smem_bytes);
    attn_kernel<<<dim3(NB, BB), 512, smem_bytes>>>(q, k, v, out);
}

// round 6
// speedup vs baseline: 3.1519x; 1.3734x over previous
#include <cuda_runtime.h>
#include <cuda_bf16.h>
#include <math.h>
#include <stdint.h>

// Problem constants (fixed shapes)
#define BB 4
#define TT 4096
#define DD 1024
#define SPAN 128
#define NB (TT / SPAN)      // 32
#define MROWS (BB * TT)     // 16384

typedef unsigned short ushortx;

// Scratch (device globals: no allocation APIs allowed)
__device__ ushortx g_xh[(size_t)MROWS * DD];
__device__ ushortx g_xl[(size_t)MROWS * DD];
__device__ ushortx g_wh[(size_t)3 * DD * DD];
__device__ ushortx g_wl[(size_t)3 * DD * DD];
__device__ ushortx g_qh[(size_t)MROWS * DD];
__device__ ushortx g_ql[(size_t)MROWS * DD];
__device__ ushortx g_kh[(size_t)MROWS * DD];
__device__ ushortx g_kl[(size_t)MROWS * DD];
__device__ ushortx g_vh[(size_t)MROWS * DD];
__device__ ushortx g_vl[(size_t)MROWS * DD];

__device__ __forceinline__ uint32_t smem_u32(const void* p) {
    uint32_t a;
    asm("{ .reg .u64 t; cvta.to.shared.u64 t, %1; cvt.u32.u64 %0, t; }"
        : "=r"(a) : "l"(p));
    return a;
}

#define LDMATRIX_X4(r0, r1, r2, r3, addr) \
    asm volatile("ldmatrix.sync.aligned.m8n8.x4.shared.b16 {%0,%1,%2,%3}, [%4];" \
                 : "=r"(r0), "=r"(r1), "=r"(r2), "=r"(r3) : "r"(addr))
#define LDMATRIX_X2(r0, r1, addr) \
    asm volatile("ldmatrix.sync.aligned.m8n8.x2.shared.b16 {%0,%1}, [%2];" \
                 : "=r"(r0), "=r"(r1) : "r"(addr))
#define LDMATRIX_X2T(r0, r1, addr) \
    asm volatile("ldmatrix.sync.aligned.m8n8.x2.trans.shared.b16 {%0,%1}, [%2];" \
                 : "=r"(r0), "=r"(r1) : "r"(addr))
#define MMA_16816(c0, c1, c2, c3, a0, a1, a2, a3, b0, b1) \
    asm volatile("mma.sync.aligned.m16n8k16.row.col.f32.bf16.bf16.f32 " \
                 "{%0,%1,%2,%3}, {%4,%5,%6,%7}, {%8,%9}, {%0,%1,%2,%3};" \
                 : "+f"(c0), "+f"(c1), "+f"(c2), "+f"(c3) \
                 : "r"(a0), "r"(a1), "r"(a2), "r"(a3), "r"(b0), "r"(b1))
#define CP_ASYNC_16(dst, src) \
    asm volatile("cp.async.cg.shared.global [%0], [%1], 16;" \
                 :: "r"(dst), "l"(src) : "memory")
#define CP_ASYNC_COMMIT() asm volatile("cp.async.commit_group;" ::: "memory")
#define CP_ASYNC_WAIT(n)  asm volatile("cp.async.wait_group %0;" :: "n"(n) : "memory")

__device__ __forceinline__ void bfsplit(float v, ushortx& h, ushortx& l) {
    __nv_bfloat16 hb = __float2bfloat16(v);
    __nv_bfloat16 lb = __float2bfloat16(v - __bfloat162float(hb));
    h = __bfloat16_as_ushort(hb);
    l = __bfloat16_as_ushort(lb);
}

// ---------------------------------------------------------------------------
// Split fp32 -> bf16 hi + bf16 lo
// ---------------------------------------------------------------------------
__global__ __launch_bounds__(256) void split_bf16(const float* __restrict__ src,
                                                  ushortx* __restrict__ hi,
                                                  ushortx* __restrict__ lo,
                                                  int n4) {
    int i = blockIdx.x * 256 + threadIdx.x;
    if (i >= n4) return;
    float4 v = reinterpret_cast<const float4*>(src)[i];
    ushort4 hv, lv;
    bfsplit(v.x, hv.x, lv.x);
    bfsplit(v.y, hv.y, lv.y);
    bfsplit(v.z, hv.z, lv.z);
    bfsplit(v.w, hv.w, lv.w);
    reinterpret_cast<ushort4*>(hi)[i] = hv;
    reinterpret_cast<ushort4*>(lo)[i] = lv;
}

// ---------------------------------------------------------------------------
// Split-bf16 tensor-core GEMM (ldmatrix + mma.sync):
//   out = x @ W^T + bias, emitted as bf16 hi/lo pairs for the attention stage.
// CTA tile M=128, N=128, K-chunk 64 (128B rows, SW128 swizzle).
// 256 threads = 8 warps (2x4), warp tile 64x32. cp.async double buffer.
// ---------------------------------------------------------------------------
struct GemmArgs {
    const ushortx* xh;
    const ushortx* xl;
    const ushortx* wh[3];
    const ushortx* wl[3];
    const float* bias[3];
    ushortx* outh[3];
    ushortx* outl[3];
};

#define TILE_BYTES 16384u        // 128 rows x 128B (64 bf16)
#define STAGE_BYTES (4u * TILE_BYTES)
#define NUM_CHUNKS (DD / 64)     // 16
#define GEMM_DSMEM (2u * STAGE_BYTES)

__global__ __launch_bounds__(256) void qkv_tc_gemm(GemmArgs args) {
    extern __shared__ char dsm[];
    const int tid = threadIdx.x;
    const int wid = tid >> 5;
    const int lane = tid & 31;
    const int bn = blockIdx.x * 128;
    const int bm = blockIdx.y * 128;
    const int z  = blockIdx.z;
    const int warp_m = wid >> 2;
    const int warp_n = wid & 3;

    const uint32_t smem_base = smem_u32(dsm);

    const ushortx* srcs[4] = {
        args.xh    + (size_t)bm * DD,
        args.xl    + (size_t)bm * DD,
        args.wh[z] + (size_t)bn * DD,
        args.wl[z] + (size_t)bn * DD };

    uint32_t ld_dst[4];
    uint32_t ld_row[4], ld_ch[4];
#pragma unroll
    for (int i = 0; i < 4; ++i) {
        int idx = tid + i * 256;
        int r = idx >> 3, ch = idx & 7;
        ld_row[i] = r; ld_ch[i] = ch;
        ld_dst[i] = (uint32_t)(r * 128 + ((ch ^ (r & 7)) * 16));
    }

    auto load_stage = [&](int c, int buf) {
        const int k0 = c * 64;
        const uint32_t sb = smem_base + buf * STAGE_BYTES;
#pragma unroll
        for (int t = 0; t < 4; ++t) {
            const ushortx* p = srcs[t] + k0;
            const uint32_t tb = sb + t * TILE_BYTES;
#pragma unroll
            for (int i = 0; i < 4; ++i) {
                const ushortx* src = p + (size_t)ld_row[i] * DD + ld_ch[i] * 8;
                CP_ASYNC_16(tb + ld_dst[i], src);
            }
        }
        CP_ASYNC_COMMIT();
    };

    float acc[4][4][4];
#pragma unroll
    for (int mt = 0; mt < 4; ++mt)
#pragma unroll
        for (int nt = 0; nt < 4; ++nt)
#pragma unroll
            for (int j = 0; j < 4; ++j) acc[mt][nt][j] = 0.0f;

    const int a_row = warp_m * 64 + (lane & 15);
    const uint32_t a_sw = (uint32_t)((a_row & 7) * 16);
    const uint32_t a_kb_lane = (uint32_t)((lane >> 4) * 16);
    const int b_row = warp_n * 32 + (lane & 7);
    const uint32_t b_sw = (uint32_t)((b_row & 7) * 16);
    const uint32_t b_kb_lane = (uint32_t)(((lane >> 3) & 1) * 16);

    load_stage(0, 0);

    for (int c = 0; c < NUM_CHUNKS; ++c) {
        const int buf = c & 1;
        if (c + 1 < NUM_CHUNKS) {
            load_stage(c + 1, (c + 1) & 1);
            CP_ASYNC_WAIT(1);
        } else {
            CP_ASYNC_WAIT(0);
        }
        __syncthreads();

        const uint32_t sb = smem_base + buf * STAGE_BYTES;
        const uint32_t a_base_h = sb + 0 * TILE_BYTES + a_row * 128;
        const uint32_t a_base_l = sb + 1 * TILE_BYTES + a_row * 128;
        const uint32_t b_base_h = sb + 2 * TILE_BYTES + b_row * 128;
        const uint32_t b_base_l = sb + 3 * TILE_BYTES + b_row * 128;

#pragma unroll
        for (int ks = 0; ks < 4; ++ks) {
            const uint32_t akb = (uint32_t)(ks * 32) + a_kb_lane;
            const uint32_t bkb = (uint32_t)(ks * 32) + b_kb_lane;
            uint32_t ah[4][4], al[4][4];
#pragma unroll
            for (int mt = 0; mt < 4; ++mt) {
                const uint32_t moff = (uint32_t)(mt * 16 * 128);
                LDMATRIX_X4(ah[mt][0], ah[mt][1], ah[mt][2], ah[mt][3],
                            a_base_h + moff + (akb ^ a_sw));
                LDMATRIX_X4(al[mt][0], al[mt][1], al[mt][2], al[mt][3],
                            a_base_l + moff + (akb ^ a_sw));
            }
#pragma unroll
            for (int nt = 0; nt < 4; ++nt) {
                const uint32_t noff = (uint32_t)(nt * 8 * 128);
                uint32_t bh0, bh1, bl0, bl1;
                LDMATRIX_X2(bh0, bh1, b_base_h + noff + (bkb ^ b_sw));
                LDMATRIX_X2(bl0, bl1, b_base_l + noff + (bkb ^ b_sw));
#pragma unroll
                for (int mt = 0; mt < 4; ++mt) {
                    MMA_16816(acc[mt][nt][0], acc[mt][nt][1], acc[mt][nt][2], acc[mt][nt][3],
                              ah[mt][0], ah[mt][1], ah[mt][2], ah[mt][3], bh0, bh1);
                    MMA_16816(acc[mt][nt][0], acc[mt][nt][1], acc[mt][nt][2], acc[mt][nt][3],
                              ah[mt][0], ah[mt][1], ah[mt][2], ah[mt][3], bl0, bl1);
                    MMA_16816(acc[mt][nt][0], acc[mt][nt][1], acc[mt][nt][2], acc[mt][nt][3],
                              al[mt][0], al[mt][1], al[mt][2], al[mt][3], bh0, bh1);
                }
            }
        }
        __syncthreads();
    }

    // Epilogue: add bias, split to bf16 hi/lo, store
    const float* bias = args.bias[z];
    ushortx* outh = args.outh[z];
    ushortx* outl = args.outl[z];
    const int er = bm + warp_m * 64 + (lane >> 2);
    const int ec = bn + warp_n * 32 + (lane & 3) * 2;
#pragma unroll
    for (int mt = 0; mt < 4; ++mt) {
#pragma unroll
        for (int nt = 0; nt < 4; ++nt) {
            const int r0 = er + mt * 16;
            const int cc = ec + nt * 8;
            float v0 = acc[mt][nt][0] + bias[cc];
            float v1 = acc[mt][nt][1] + bias[cc + 1];
            float v2 = acc[mt][nt][2] + bias[cc];
            float v3 = acc[mt][nt][3] + bias[cc + 1];
            ushort2 h01, l01, h23, l23;
            bfsplit(v0, h01.x, l01.x); bfsplit(v1, h01.y, l01.y);
            bfsplit(v2, h23.x, l23.x); bfsplit(v3, h23.y, l23.y);
            *reinterpret_cast<ushort2*>(outh + (size_t)r0 * DD + cc) = h01;
            *reinterpret_cast<ushort2*>(outl + (size_t)r0 * DD + cc) = l01;
            *reinterpret_cast<ushort2*>(outh + (size_t)(r0 + 8) * DD + cc) = h23;
            *reinterpret_cast<ushort2*>(outl + (size_t)(r0 + 8) * DD + cc) = l23;
        }
    }
}

// ---------------------------------------------------------------------------
// Tensor-core windowed attention. One CTA per (b, n): 128 q rows x 256 keys.
// Phase 1: S = Qh@Kh' + Qh@Kl' + Ql@Kh'  (regs, warp tile 64x64)
// Phase 2: register softmax, cross-warp reduce via smem; P -> bf16 h/l smem
// Phase 3: O = Ph@Vh + Ph@Vl + Pl@Vh  (V streamed, ldmatrix.trans B frags)
// 256 threads = 8 warps (2 m x 4 n). dsmem 192KB.
// ---------------------------------------------------------------------------
struct AttnArgs {
    const ushortx *qh, *ql, *kh, *kl, *vh, *vl;
    float* out;
};

#define A_STAGE 98304u             // Qh 16K | Ql 16K | Kh 32K | Kl 32K
#define A_QH 0u
#define A_QL 16384u
#define A_KH 32768u
#define A_KL 65536u
#define P_H  0u                    // phase 3: Ph 64K
#define P_L  65536u                //          Pl 64K
#define V_BASE 131072u             //          V stages: 2 x (Vh 16K + Vl 16K)
#define ATTN_DSMEM 196608u

__global__ __launch_bounds__(256) void attn_tc(AttnArgs a) {
    extern __shared__ char dsm[];
    __shared__ float redmax[128][4];
    __shared__ float redsum[128][4];

    const int tid = threadIdx.x;
    const int wid = tid >> 5;
    const int lane = tid & 31;
    const int wm = wid >> 2;        // 0..1
    const int wn = wid & 3;         // 0..3
    const int nblk = blockIdx.x;
    const int b = blockIdx.y;
    const size_t qrow0 = (size_t)b * TT + (size_t)nblk * SPAN;
    const int kv0 = (nblk - 1) * SPAN;
    const uint32_t smem = smem_u32(dsm);

    // ---------------- Phase 1: S = Q @ K^T (3-term split) ----------------
    float acc[4][8][4];
#pragma unroll
    for (int mt = 0; mt < 4; ++mt)
#pragma unroll
        for (int nt = 0; nt < 8; ++nt)
#pragma unroll
            for (int j = 0; j < 4; ++j) acc[mt][nt][j] = 0.0f;

    auto load_stage1 = [&](int c, int buf) {
        const int k0 = c * 64;
        const uint32_t sb = smem + buf * A_STAGE;
        // Q tiles: 128 rows
#pragma unroll
        for (int i = 0; i < 4; ++i) {
            int idx = tid + i * 256;
            int r = idx >> 3, ch = idx & 7;
            uint32_t dst = (uint32_t)(r * 128 + ((ch ^ (r & 7)) * 16));
            const size_t goff = (qrow0 + r) * DD + k0 + ch * 8;
            CP_ASYNC_16(sb + A_QH + dst, a.qh + goff);
            CP_ASYNC_16(sb + A_QL + dst, a.ql + goff);
        }
        // K tiles: 256 rows (clamped)
#pragma unroll
        for (int i = 0; i < 8; ++i) {
            int idx = tid + i * 256;
            int r = idx >> 3, ch = idx & 7;
            int krow = kv0 + r; if (krow < 0) krow = 0;
            uint32_t dst = (uint32_t)(r * 128 + ((ch ^ (r & 7)) * 16));
            const size_t goff = ((size_t)b * TT + krow) * DD + k0 + ch * 8;
            CP_ASYNC_16(sb + A_KH + dst, a.kh + goff);
            CP_ASYNC_16(sb + A_KL + dst, a.kl + goff);
        }
        CP_ASYNC_COMMIT();
    };

    const int a_row = wm * 64 + (lane & 15);
    const uint32_t a_sw = (uint32_t)((a_row & 7) * 16);
    const uint32_t a_kb_lane = (uint32_t)((lane >> 4) * 16);
    const uint32_t b_sw = (uint32_t)((lane & 7) * 16);
    const uint32_t b_kb_lane = (uint32_t)(((lane >> 3) & 1) * 16);

    load_stage1(0, 0);

    for (int c = 0; c < NUM_CHUNKS; ++c) {
        const int buf = c & 1;
        if (c + 1 < NUM_CHUNKS) {
            load_stage1(c + 1, (c + 1) & 1);
            CP_ASYNC_WAIT(1);
        } else {
            CP_ASYNC_WAIT(0);
        }
        __syncthreads();

        const uint32_t sb = smem + buf * A_STAGE;
        const uint32_t a_base_h = sb + A_QH + a_row * 128;
        const uint32_t a_base_l = sb + A_QL + a_row * 128;

#pragma unroll
        for (int ks = 0; ks < 4; ++ks) {
            const uint32_t akb = (uint32_t)(ks * 32) + a_kb_lane;
            const uint32_t bkb = (uint32_t)(ks * 32) + b_kb_lane;
            uint32_t ah[4][4], al[4][4];
#pragma unroll
            for (int mt = 0; mt < 4; ++mt) {
                const uint32_t moff = (uint32_t)(mt * 16 * 128);
                LDMATRIX_X4(ah[mt][0], ah[mt][1], ah[mt][2], ah[mt][3],
                            a_base_h + moff + (akb ^ a_sw));
                LDMATRIX_X4(al[mt][0], al[mt][1], al[mt][2], al[mt][3],
                            a_base_l + moff + (akb ^ a_sw));
            }
#pragma unroll
            for (int nt = 0; nt < 8; ++nt) {
                const int brow = wn * 64 + nt * 8 + (lane & 7);
                const uint32_t boff = (uint32_t)(brow * 128) + (bkb ^ b_sw);
                uint32_t bh0, bh1, bl0, bl1;
                LDMATRIX_X2(bh0, bh1, sb + A_KH + boff);
                LDMATRIX_X2(bl0, bl1, sb + A_KL + boff);
#pragma unroll
                for (int mt = 0; mt < 4; ++mt) {
                    MMA_16816(acc[mt][nt][0], acc[mt][nt][1], acc[mt][nt][2], acc[mt][nt][3],
                              ah[mt][0], ah[mt][1], ah[mt][2], ah[mt][3], bh0, bh1);
                    MMA_16816(acc[mt][nt][0], acc[mt][nt][1], acc[mt][nt][2], acc[mt][nt][3],
                              ah[mt][0], ah[mt][1], ah[mt][2], ah[mt][3], bl0, bl1);
                    MMA_16816(acc[mt][nt][0], acc[mt][nt][1], acc[mt][nt][2], acc[mt][nt][3],
                              al[mt][0], al[mt][1], al[mt][2], al[mt][3], bh0, bh1);
                }
            }
        }
        __syncthreads();
    }

    // ---------------- Phase 2: register softmax ----------------
    const float scale = 0.03125f;   // 1/sqrt(1024)
    float rmax[4][2];
#pragma unroll
    for (int mt = 0; mt < 4; ++mt) {
#pragma unroll
        for (int half = 0; half < 2; ++half) {
            const int row = wm * 64 + mt * 16 + half * 8 + (lane >> 2);
            float m = -1e30f;
#pragma unroll
            for (int nt = 0; nt < 8; ++nt) {
#pragma unroll
                for (int j = 0; j < 2; ++j) {
                    const int col = wn * 64 + nt * 8 + (lane & 3) * 2 + j;
                    const bool ok = (col > row) && (col <= row + SPAN) &&
                                    (nblk > 0 || col >= SPAN);
                    float s = ok ? acc[mt][nt][half * 2 + j] * scale : -1e30f;
                    acc[mt][nt][half * 2 + j] = s;
                    m = fmaxf(m, s);
                }
            }
            m = fmaxf(m, __shfl_xor_sync(0xFFFFFFFFu, m, 1));
            m = fmaxf(m, __shfl_xor_sync(0xFFFFFFFFu, m, 2));
            if ((lane & 3) == 0) redmax[row][wn] = m;
        }
    }
    __syncthreads();
#pragma unroll
    for (int mt = 0; mt < 4; ++mt) {
#pragma unroll
        for (int half = 0; half < 2; ++half) {
            const int row = wm * 64 + mt * 16 + half * 8 + (lane >> 2);
            float m = fmaxf(fmaxf(redmax[row][0], redmax[row][1]),
                            fmaxf(redmax[row][2], redmax[row][3]));
            rmax[mt][half] = m;
            float sum = 0.0f;
#pragma unroll
            for (int nt = 0; nt < 8; ++nt) {
#pragma unroll
                for (int j = 0; j < 2; ++j) {
                    float s = acc[mt][nt][half * 2 + j];
                    float p = (s > -1e29f) ? __expf(s - m) : 0.0f;
                    acc[mt][nt][half * 2 + j] = p;
                    sum += p;
                }
            }
            sum += __shfl_xor_sync(0xFFFFFFFFu, sum, 1);
            sum += __shfl_xor_sync(0xFFFFFFFFu, sum, 2);
            if ((lane & 3) == 0) redsum[row][wn] = sum;
        }
    }
    __syncthreads();
    // Write P (bf16 hi/lo) to smem with 512B-row swizzle
#pragma unroll
    for (int mt = 0; mt < 4; ++mt) {
#pragma unroll
        for (int half = 0; half < 2; ++half) {
            const int row = wm * 64 + mt * 16 + half * 8 + (lane >> 2);
            const float inv = 1.0f / (redsum[row][0] + redsum[row][1] +
                                      redsum[row][2] + redsum[row][3]);
#pragma unroll
            for (int nt = 0; nt < 8; ++nt) {
                const int col = wn * 64 + nt * 8 + (lane & 3) * 2;
                float p0 = acc[mt][nt][half * 2 + 0] * inv;
                float p1 = acc[mt][nt][half * 2 + 1] * inv;
                ushort2 h, l;
                bfsplit(p0, h.x, l.x);
                bfsplit(p1, h.y, l.y);
                uint32_t off = (uint32_t)(row * 512 + col * 2);
                off ^= (off >> 5) & 0x70;
                asm volatile("st.shared.b32 [%0], %1;"
                             :: "r"(smem + P_H + off), "r"(*(uint32_t*)&h) : "memory");
                asm volatile("st.shared.b32 [%0], %1;"
                             :: "r"(smem + P_L + off), "r"(*(uint32_t*)&l) : "memory");
            }
        }
    }
    __syncthreads();

    // ---------------- Phase 3: O = P @ V (3-term split) ----------------
    auto load_v = [&](int kc, int buf, int d0) {
        const uint32_t sb = smem + V_BASE + buf * 32768u;
#pragma unroll
        for (int i = 0; i < 4; ++i) {
            int idx = tid + i * 256;
            int r = idx >> 5, ch = idx & 31;
            int vrow = kv0 + kc * 32 + r; if (vrow < 0) vrow = 0;
            uint32_t dst = (uint32_t)(r * 512 + ((ch ^ (r & 7)) * 16));
            const size_t goff = ((size_t)b * TT + vrow) * DD + d0 + ch * 8;
            CP_ASYNC_16(sb + dst, a.vh + goff);
            CP_ASYNC_16(sb + 16384u + dst, a.vl + goff);
        }
        CP_ASYNC_COMMIT();
    };

    for (int dc = 0; dc < 4; ++dc) {
        const int d0 = dc * 256;
        float acc2[4][8][4];
#pragma unroll
        for (int mt = 0; mt < 4; ++mt)
#pragma unroll
            for (int nt = 0; nt < 8; ++nt)
#pragma unroll
                for (int j = 0; j < 4; ++j) acc2[mt][nt][j] = 0.0f;

        load_v(0, 0, d0);
        for (int kc = 0; kc < 8; ++kc) {
            const int buf = kc & 1;
            if (kc + 1 < 8) {
                load_v(kc + 1, (kc + 1) & 1, d0);
                CP_ASYNC_WAIT(1);
            } else {
                CP_ASYNC_WAIT(0);
            }
            __syncthreads();

            const uint32_t vb = smem + V_BASE + buf * 32768u;
#pragma unroll
            for (int ks = 0; ks < 2; ++ks) {
                const int kbase = kc * 32 + ks * 16;
                uint32_t ph[4][4], pl[4][4];
#pragma unroll
                for (int mt = 0; mt < 4; ++mt) {
                    const int prow = wm * 64 + mt * 16 + (lane & 15);
                    uint32_t aoff = (uint32_t)(prow * 512 + kbase * 2 + (lane >> 4) * 16);
                    aoff ^= (aoff >> 5) & 0x70;
                    LDMATRIX_X4(ph[mt][0], ph[mt][1], ph[mt][2], ph[mt][3], smem + P_H + aoff);
                    LDMATRIX_X4(pl[mt][0], pl[mt][1], pl[mt][2], pl[mt][3], smem + P_L + aoff);
                }
#pragma unroll
                for (int nt = 0; nt < 8; ++nt) {
                    const int vrow = ks * 16 + (lane & 15);
                    uint32_t boff = (uint32_t)(vrow * 512 + (wn * 64 + nt * 8) * 2);
                    boff ^= (boff >> 5) & 0x70;
                    uint32_t vh0, vh1, vl0, vl1;
                    LDMATRIX_X2T(vh0, vh1, vb + boff);
                    LDMATRIX_X2T(vl0, vl1, vb + 16384u + boff);
#pragma unroll
                    for (int mt = 0; mt < 4; ++mt) {
                        MMA_16816(acc2[mt][nt][0], acc2[mt][nt][1], acc2[mt][nt][2], acc2[mt][nt][3],
                                  ph[mt][0], ph[mt][1], ph[mt][2], ph[mt][3], vh0, vh1);
                        MMA_16816(acc2[mt][nt][0], acc2[mt][nt][1], acc2[mt][nt][2], acc2[mt][nt][3],
                                  ph[mt][0], ph[mt][1], ph[mt][2], ph[mt][3], vl0, vl1);
                        MMA_16816(acc2[mt][nt][0], acc2[mt][nt][1], acc2[mt][nt][2], acc2[mt][nt][3],
                                  pl[mt][0], pl[mt][1], pl[mt][2], pl[mt][3], vh0, vh1);
                    }
                }
            }
            __syncthreads();
        }

        // Epilogue for this d-chunk
#pragma unroll
        for (int mt = 0; mt < 4; ++mt) {
#pragma unroll
            for (int nt = 0; nt < 8; ++nt) {
                const size_t row = qrow0 + wm * 64 + mt * 16 + (lane >> 2);
                const int col = d0 + wn * 64 + nt * 8 + (lane & 3) * 2;
                float2 v0 = make_float2(acc2[mt][nt][0], acc2[mt][nt][1]);
                float2 v1 = make_float2(acc2[mt][nt][2], acc2[mt][nt][3]);
                *reinterpret_cast<float2*>(a.out + row * DD + col) = v0;
                *reinterpret_cast<float2*>(a.out + (row + 8) * DD + col) = v1;
            }
        }
    }
}

// ---------------------------------------------------------------------------
extern "C" void kernel_launch(void* const* d_in, const int* in_sizes, int n_in,
                              void* d_out, int out_size) {
    const float* x  = (const float*)d_in[0];
    const float* Wq = (const float*)d_in[1];
    const float* bq = (const float*)d_in[2];
    const float* Wk = (const float*)d_in[3];
    const float* bk = (const float*)d_in[4];
    const float* Wv = (const float*)d_in[5];
    const float* bv = (const float*)d_in[6];
    float* out = (float*)d_out;

    ushortx *xh, *xl, *wh, *wl, *qh, *ql, *kh, *kl, *vh, *vl;
    cudaGetSymbolAddress((void**)&xh, g_xh);
    cudaGetSymbolAddress((void**)&xl, g_xl);
    cudaGetSymbolAddress((void**)&wh, g_wh);
    cudaGetSymbolAddress((void**)&wl, g_wl);
    cudaGetSymbolAddress((void**)&qh, g_qh);
    cudaGetSymbolAddress((void**)&ql, g_ql);
    cudaGetSymbolAddress((void**)&kh, g_kh);
    cudaGetSymbolAddress((void**)&kl, g_kl);
    cudaGetSymbolAddress((void**)&vh, g_vh);
    cudaGetSymbolAddress((void**)&vl, g_vl);

    // Split fp32 -> bf16 hi/lo
    {
        int n4 = MROWS * DD / 4;
        split_bf16<<<(n4 + 255) / 256, 256>>>(x, xh, xl, n4);
        int w4 = DD * DD / 4;
        split_bf16<<<(w4 + 255) / 256, 256>>>(Wq, wh + 0 * (size_t)DD * DD, wl + 0 * (size_t)DD * DD, w4);
        split_bf16<<<(w4 + 255) / 256, 256>>>(Wk, wh + 1 * (size_t)DD * DD, wl + 1 * (size_t)DD * DD, w4);
        split_bf16<<<(w4 + 255) / 256, 256>>>(Wv, wh + 2 * (size_t)DD * DD, wl + 2 * (size_t)DD * DD, w4);
    }

    GemmArgs ga;
    ga.xh = xh; ga.xl = xl;
    ga.wh[0] = wh;                       ga.wl[0] = wl;
    ga.wh[1] = wh + 1 * (size_t)DD * DD; ga.wl[1] = wl + 1 * (size_t)DD * DD;
    ga.wh[2] = wh + 2 * (size_t)DD * DD; ga.wl[2] = wl + 2 * (size_t)DD * DD;
    ga.bias[0] = bq; ga.bias[1] = bk; ga.bias[2] = bv;
    ga.outh[0] = qh; ga.outl[0] = ql;
    ga.outh[1] = kh; ga.outl[1] = kl;
    ga.outh[2] = vh; ga.outl[2] = vl;

    cudaFuncSetAttribute(qkv_tc_gemm, cudaFuncAttributeMaxDynamicSharedMemorySize,
                         GEMM_DSMEM);
    qkv_tc_gemm<<<dim3(DD / 128, MROWS / 128, 3), 256, GEMM_DSMEM>>>(ga);

    AttnArgs aa;
    aa.qh = qh; aa.ql = ql; aa.kh = kh; aa.kl = kl; aa.vh = vh; aa.vl = vl;
    aa.out = out;
    cudaFuncSetAttribute(attn_tc, cudaFuncAttributeMaxDynamicSharedMemorySize,
                         ATTN_DSMEM);
    attn_tc<<<dim3(NB, BB), 256, ATTN_DSMEM>>>(aa);
}

// round 7
// speedup vs baseline: 3.1539x; 1.0006x over previous
#include <cuda_runtime.h>
#include <cuda_bf16.h>
#include <math.h>
#include <stdint.h>

// Problem constants (fixed shapes)
#define BB 4
#define TT 4096
#define DD 1024
#define SPAN 128
#define NB (TT / SPAN)      // 32
#define MROWS (BB * TT)     // 16384

typedef unsigned short ushortx;

// Scratch (device globals: no allocation APIs allowed)
__device__ ushortx g_xh[(size_t)MROWS * DD];
__device__ ushortx g_xl[(size_t)MROWS * DD];
__device__ ushortx g_wh[(size_t)3 * DD * DD];
__device__ ushortx g_wl[(size_t)3 * DD * DD];
__device__ ushortx g_qh[(size_t)MROWS * DD];
__device__ ushortx g_ql[(size_t)MROWS * DD];
__device__ ushortx g_kh[(size_t)MROWS * DD];
__device__ ushortx g_kl[(size_t)MROWS * DD];
__device__ ushortx g_vh[(size_t)MROWS * DD];
__device__ ushortx g_vl[(size_t)MROWS * DD];

__device__ __forceinline__ uint32_t smem_u32(const void* p) {
    uint32_t a;
    asm("{ .reg .u64 t; cvta.to.shared.u64 t, %1; cvt.u32.u64 %0, t; }"
        : "=r"(a) : "l"(p));
    return a;
}

#define LDMATRIX_X4(r0, r1, r2, r3, addr) \
    asm volatile("ldmatrix.sync.aligned.m8n8.x4.shared.b16 {%0,%1,%2,%3}, [%4];" \
                 : "=r"(r0), "=r"(r1), "=r"(r2), "=r"(r3) : "r"(addr))
#define LDMATRIX_X4T(r0, r1, r2, r3, addr) \
    asm volatile("ldmatrix.sync.aligned.m8n8.x4.trans.shared.b16 {%0,%1,%2,%3}, [%4];" \
                 : "=r"(r0), "=r"(r1), "=r"(r2), "=r"(r3) : "r"(addr))
#define MMA_16816(c0, c1, c2, c3, a0, a1, a2, a3, b0, b1) \
    asm volatile("mma.sync.aligned.m16n8k16.row.col.f32.bf16.bf16.f32 " \
                 "{%0,%1,%2,%3}, {%4,%5,%6,%7}, {%8,%9}, {%0,%1,%2,%3};" \
                 : "+f"(c0), "+f"(c1), "+f"(c2), "+f"(c3) \
                 : "r"(a0), "r"(a1), "r"(a2), "r"(a3), "r"(b0), "r"(b1))
#define CP_ASYNC_16(dst, src) \
    asm volatile("cp.async.cg.shared.global [%0], [%1], 16;" \
                 :: "r"(dst), "l"(src) : "memory")
#define CP_ASYNC_COMMIT() asm volatile("cp.async.commit_group;" ::: "memory")
#define CP_ASYNC_WAIT(n)  asm volatile("cp.async.wait_group %0;" :: "n"(n) : "memory")

__device__ __forceinline__ void bfsplit(float v, ushortx& h, ushortx& l) {
    __nv_bfloat16 hb = __float2bfloat16(v);
    __nv_bfloat16 lb = __float2bfloat16(v - __bfloat162float(hb));
    h = __bfloat16_as_ushort(hb);
    l = __bfloat16_as_ushort(lb);
}

// ---------------------------------------------------------------------------
// Split fp32 -> bf16 hi + bf16 lo
// ---------------------------------------------------------------------------
__global__ __launch_bounds__(256) void split_bf16(const float* __restrict__ src,
                                                  ushortx* __restrict__ hi,
                                                  ushortx* __restrict__ lo,
                                                  int n4) {
    int i = blockIdx.x * 256 + threadIdx.x;
    if (i >= n4) return;
    float4 v = reinterpret_cast<const float4*>(src)[i];
    ushort4 hv, lv;
    bfsplit(v.x, hv.x, lv.x);
    bfsplit(v.y, hv.y, lv.y);
    bfsplit(v.z, hv.z, lv.z);
    bfsplit(v.w, hv.w, lv.w);
    reinterpret_cast<ushort4*>(hi)[i] = hv;
    reinterpret_cast<ushort4*>(lo)[i] = lv;
}

// ---------------------------------------------------------------------------
// Split-bf16 tensor-core GEMM (ldmatrix + mma.sync), 3-stage cp.async pipeline.
//   out = x @ W^T + bias, emitted as bf16 hi/lo pairs.
// CTA tile M=128, N=128, K-chunk 64; 256 threads = 8 warps, warp tile 64x32.
// ---------------------------------------------------------------------------
struct GemmArgs {
    const ushortx* xh;
    const ushortx* xl;
    const ushortx* wh[3];
    const ushortx* wl[3];
    const float* bias[3];
    ushortx* outh[3];
    ushortx* outl[3];
};

#define TILE_BYTES 16384u        // 128 rows x 128B (64 bf16)
#define STAGE_BYTES (4u * TILE_BYTES)
#define NUM_CHUNKS (DD / 64)     // 16
#define GEMM_DSMEM (3u * STAGE_BYTES)   // 192 KB

__global__ __launch_bounds__(256) void qkv_tc_gemm(GemmArgs args) {
    extern __shared__ char dsm[];
    const int tid = threadIdx.x;
    const int wid = tid >> 5;
    const int lane = tid & 31;
    const int bn = blockIdx.x * 128;
    const int bm = blockIdx.y * 128;
    const int z  = blockIdx.z;
    const int warp_m = wid >> 2;
    const int warp_n = wid & 3;

    const uint32_t smem_base = smem_u32(dsm);

    const ushortx* srcs[4] = {
        args.xh    + (size_t)bm * DD,
        args.xl    + (size_t)bm * DD,
        args.wh[z] + (size_t)bn * DD,
        args.wl[z] + (size_t)bn * DD };

    uint32_t ld_dst[4];
    uint32_t ld_row[4], ld_ch[4];
#pragma unroll
    for (int i = 0; i < 4; ++i) {
        int idx = tid + i * 256;
        int r = idx >> 3, ch = idx & 7;
        ld_row[i] = r; ld_ch[i] = ch;
        ld_dst[i] = (uint32_t)(r * 128 + ((ch ^ (r & 7)) * 16));
    }

    auto load_stage = [&](int c, int buf) {
        const int k0 = c * 64;
        const uint32_t sb = smem_base + buf * STAGE_BYTES;
#pragma unroll
        for (int t = 0; t < 4; ++t) {
            const ushortx* p = srcs[t] + k0;
            const uint32_t tb = sb + t * TILE_BYTES;
#pragma unroll
            for (int i = 0; i < 4; ++i) {
                const ushortx* src = p + (size_t)ld_row[i] * DD + ld_ch[i] * 8;
                CP_ASYNC_16(tb + ld_dst[i], src);
            }
        }
        CP_ASYNC_COMMIT();
    };

    float acc[4][4][4];
#pragma unroll
    for (int mt = 0; mt < 4; ++mt)
#pragma unroll
        for (int nt = 0; nt < 4; ++nt)
#pragma unroll
            for (int j = 0; j < 4; ++j) acc[mt][nt][j] = 0.0f;

    // A (x4): row = warpm*64 + mt*16 + (lane&15), koff = (lane>>4)*16
    const int a_row = warp_m * 64 + (lane & 15);
    const uint32_t a_sw = (uint32_t)((a_row & 7) * 16);
    const uint32_t a_kb_lane = (uint32_t)((lane >> 4) * 16);
    // B (x4, 16 n-rows per load): row = warpn*32 + ntp*16 + (lane&7) + (lane>>4)*8
    const int b_row2 = warp_n * 32 + (lane & 7) + ((lane >> 4) << 3);
    const uint32_t b_koff = (uint32_t)(((lane >> 3) & 1) * 16);
    const uint32_t b_sw2 = (uint32_t)((lane & 7) * 16);

    load_stage(0, 0);
    load_stage(1, 1);

    for (int c = 0; c < NUM_CHUNKS; ++c) {
        if (c + 1 < NUM_CHUNKS) { CP_ASYNC_WAIT(1); } else { CP_ASYNC_WAIT(0); }
        __syncthreads();
        if (c + 2 < NUM_CHUNKS) load_stage(c + 2, (c + 2) % 3);

        const uint32_t sb = smem_base + (c % 3) * STAGE_BYTES;
        const uint32_t a_base_h = sb + 0 * TILE_BYTES + a_row * 128;
        const uint32_t a_base_l = sb + 1 * TILE_BYTES + a_row * 128;
        const uint32_t b_tile_h = sb + 2 * TILE_BYTES;
        const uint32_t b_tile_l = sb + 3 * TILE_BYTES;

#pragma unroll
        for (int ks = 0; ks < 4; ++ks) {
            const uint32_t akb = (uint32_t)(ks * 32) + a_kb_lane;
            uint32_t ah[4][4], al[4][4];
#pragma unroll
            for (int mt = 0; mt < 4; ++mt) {
                const uint32_t moff = (uint32_t)(mt * 16 * 128);
                LDMATRIX_X4(ah[mt][0], ah[mt][1], ah[mt][2], ah[mt][3],
                            a_base_h + moff + (akb ^ a_sw));
                LDMATRIX_X4(al[mt][0], al[mt][1], al[mt][2], al[mt][3],
                            a_base_l + moff + (akb ^ a_sw));
            }
#pragma unroll
            for (int ntp = 0; ntp < 2; ++ntp) {
                const uint32_t ba = (uint32_t)((b_row2 + ntp * 16) * 128) +
                                    (((uint32_t)(ks * 32) + b_koff) ^ b_sw2);
                uint32_t bh0, bh1, bh2, bh3, bl0, bl1, bl2, bl3;
                LDMATRIX_X4(bh0, bh1, bh2, bh3, b_tile_h + ba);
                LDMATRIX_X4(bl0, bl1, bl2, bl3, b_tile_l + ba);
                const int n0 = ntp * 2, n1 = ntp * 2 + 1;
#pragma unroll
                for (int mt = 0; mt < 4; ++mt) {
                    MMA_16816(acc[mt][n0][0], acc[mt][n0][1], acc[mt][n0][2], acc[mt][n0][3],
                              ah[mt][0], ah[mt][1], ah[mt][2], ah[mt][3], bh0, bh1);
                    MMA_16816(acc[mt][n0][0], acc[mt][n0][1], acc[mt][n0][2], acc[mt][n0][3],
                              ah[mt][0], ah[mt][1], ah[mt][2], ah[mt][3], bl0, bl1);
                    MMA_16816(acc[mt][n0][0], acc[mt][n0][1], acc[mt][n0][2], acc[mt][n0][3],
                              al[mt][0], al[mt][1], al[mt][2], al[mt][3], bh0, bh1);
                    MMA_16816(acc[mt][n1][0], acc[mt][n1][1], acc[mt][n1][2], acc[mt][n1][3],
                              ah[mt][0], ah[mt][1], ah[mt][2], ah[mt][3], bh2, bh3);
                    MMA_16816(acc[mt][n1][0], acc[mt][n1][1], acc[mt][n1][2], acc[mt][n1][3],
                              ah[mt][0], ah[mt][1], ah[mt][2], ah[mt][3], bl2, bl3);
                    MMA_16816(acc[mt][n1][0], acc[mt][n1][1], acc[mt][n1][2], acc[mt][n1][3],
                              al[mt][0], al[mt][1], al[mt][2], al[mt][3], bh2, bh3);
                }
            }
        }
    }
    __syncthreads();

    // Epilogue: add bias, split to bf16 hi/lo, store
    const float* bias = args.bias[z];
    ushortx* outh = args.outh[z];
    ushortx* outl = args.outl[z];
    const int er = bm + warp_m * 64 + (lane >> 2);
    const int ec = bn + warp_n * 32 + (lane & 3) * 2;
#pragma unroll
    for (int mt = 0; mt < 4; ++mt) {
#pragma unroll
        for (int nt = 0; nt < 4; ++nt) {
            const int r0 = er + mt * 16;
            const int cc = ec + nt * 8;
            float v0 = acc[mt][nt][0] + bias[cc];
            float v1 = acc[mt][nt][1] + bias[cc + 1];
            float v2 = acc[mt][nt][2] + bias[cc];
            float v3 = acc[mt][nt][3] + bias[cc + 1];
            ushort2 h01, l01, h23, l23;
            bfsplit(v0, h01.x, l01.x); bfsplit(v1, h01.y, l01.y);
            bfsplit(v2, h23.x, l23.x); bfsplit(v3, h23.y, l23.y);
            *reinterpret_cast<ushort2*>(outh + (size_t)r0 * DD + cc) = h01;
            *reinterpret_cast<ushort2*>(outl + (size_t)r0 * DD + cc) = l01;
            *reinterpret_cast<ushort2*>(outh + (size_t)(r0 + 8) * DD + cc) = h23;
            *reinterpret_cast<ushort2*>(outl + (size_t)(r0 + 8) * DD + cc) = l23;
        }
    }
}

// ---------------------------------------------------------------------------
// Tensor-core windowed attention with masked-tile skipping.
// One CTA per (b, n): 128 q rows x 256 keys. 8 warps (2 m x 4 n).
// ---------------------------------------------------------------------------
struct AttnArgs {
    const ushortx *qh, *ql, *kh, *kl, *vh, *vl;
    float* out;
};

#define A_STAGE 98304u             // Qh 16K | Ql 16K | Kh 32K | Kl 32K
#define A_QH 0u
#define A_QL 16384u
#define A_KH 32768u
#define A_KL 65536u
#define P_H  0u                    // phase 3: Ph 64K
#define P_L  65536u                //          Pl 64K
#define V_BASE 131072u             //          V stages: 2 x (Vh 16K + Vl 16K)
#define ATTN_DSMEM 196608u

__global__ __launch_bounds__(256) void attn_tc(AttnArgs a) {
    extern __shared__ char dsm[];
    __shared__ float redmax[128][4];
    __shared__ float redsum[128][4];

    const int tid = threadIdx.x;
    const int wid = tid >> 5;
    const int lane = tid & 31;
    const int wm = wid >> 2;        // 0..1
    const int wn = wid & 3;         // 0..3
    const int nblk = blockIdx.x;
    const int b = blockIdx.y;
    const size_t qrow0 = (size_t)b * TT + (size_t)nblk * SPAN;
    const int kv0 = (nblk - 1) * SPAN;
    const uint32_t smem = smem_u32(dsm);

    // Fully-masked warp tile in phase 1?
    const bool s1skip = ((wn * 64 + 63) <= (wm * 64)) ||
                        ((wn * 64) > (wm * 64 + 191)) ||
                        (nblk == 0 && wn < 2);

    // ---------------- Phase 1: S = Q @ K^T (3-term split) ----------------
    float acc[4][8][4];
#pragma unroll
    for (int mt = 0; mt < 4; ++mt)
#pragma unroll
        for (int nt = 0; nt < 8; ++nt)
#pragma unroll
            for (int j = 0; j < 4; ++j) acc[mt][nt][j] = 0.0f;

    auto load_stage1 = [&](int c, int buf) {
        const int k0 = c * 64;
        const uint32_t sb = smem + buf * A_STAGE;
#pragma unroll
        for (int i = 0; i < 4; ++i) {
            int idx = tid + i * 256;
            int r = idx >> 3, ch = idx & 7;
            uint32_t dst = (uint32_t)(r * 128 + ((ch ^ (r & 7)) * 16));
            const size_t goff = (qrow0 + r) * DD + k0 + ch * 8;
            CP_ASYNC_16(sb + A_QH + dst, a.qh + goff);
            CP_ASYNC_16(sb + A_QL + dst, a.ql + goff);
        }
#pragma unroll
        for (int i = 0; i < 8; ++i) {
            int idx = tid + i * 256;
            int r = idx >> 3, ch = idx & 7;
            int krow = kv0 + r; if (krow < 0) krow = 0;
            uint32_t dst = (uint32_t)(r * 128 + ((ch ^ (r & 7)) * 16));
            const size_t goff = ((size_t)b * TT + krow) * DD + k0 + ch * 8;
            CP_ASYNC_16(sb + A_KH + dst, a.kh + goff);
            CP_ASYNC_16(sb + A_KL + dst, a.kl + goff);
        }
        CP_ASYNC_COMMIT();
    };

    const int a_row = wm * 64 + (lane & 15);
    const uint32_t a_sw = (uint32_t)((a_row & 7) * 16);
    const uint32_t a_kb_lane = (uint32_t)((lane >> 4) * 16);
    const int b_row2 = wn * 64 + (lane & 7) + ((lane >> 4) << 3);
    const uint32_t b_koff = (uint32_t)(((lane >> 3) & 1) * 16);
    const uint32_t b_sw2 = (uint32_t)((lane & 7) * 16);

    load_stage1(0, 0);

    for (int c = 0; c < NUM_CHUNKS; ++c) {
        const int buf = c & 1;
        if (c + 1 < NUM_CHUNKS) {
            load_stage1(c + 1, (c + 1) & 1);
            CP_ASYNC_WAIT(1);
        } else {
            CP_ASYNC_WAIT(0);
        }
        __syncthreads();

        if (!s1skip) {
            const uint32_t sb = smem + buf * A_STAGE;
            const uint32_t a_base_h = sb + A_QH + a_row * 128;
            const uint32_t a_base_l = sb + A_QL + a_row * 128;

#pragma unroll
            for (int ks = 0; ks < 4; ++ks) {
                const uint32_t akb = (uint32_t)(ks * 32) + a_kb_lane;
                uint32_t ah[4][4], al[4][4];
#pragma unroll
                for (int mt = 0; mt < 4; ++mt) {
                    const uint32_t moff = (uint32_t)(mt * 16 * 128);
                    LDMATRIX_X4(ah[mt][0], ah[mt][1], ah[mt][2], ah[mt][3],
                                a_base_h + moff + (akb ^ a_sw));
                    LDMATRIX_X4(al[mt][0], al[mt][1], al[mt][2], al[mt][3],
                                a_base_l + moff + (akb ^ a_sw));
                }
#pragma unroll
                for (int ntp = 0; ntp < 4; ++ntp) {
                    const uint32_t ba = (uint32_t)((b_row2 + ntp * 16) * 128) +
                                        (((uint32_t)(ks * 32) + b_koff) ^ b_sw2);
                    uint32_t bh0, bh1, bh2, bh3, bl0, bl1, bl2, bl3;
                    LDMATRIX_X4(bh0, bh1, bh2, bh3, sb + A_KH + ba);
                    LDMATRIX_X4(bl0, bl1, bl2, bl3, sb + A_KL + ba);
                    const int n0 = ntp * 2, n1 = ntp * 2 + 1;
#pragma unroll
                    for (int mt = 0; mt < 4; ++mt) {
                        MMA_16816(acc[mt][n0][0], acc[mt][n0][1], acc[mt][n0][2], acc[mt][n0][3],
                                  ah[mt][0], ah[mt][1], ah[mt][2], ah[mt][3], bh0, bh1);
                        MMA_16816(acc[mt][n0][0], acc[mt][n0][1], acc[mt][n0][2], acc[mt][n0][3],
                                  ah[mt][0], ah[mt][1], ah[mt][2], ah[mt][3], bl0, bl1);
                        MMA_16816(acc[mt][n0][0], acc[mt][n0][1], acc[mt][n0][2], acc[mt][n0][3],
                                  al[mt][0], al[mt][1], al[mt][2], al[mt][3], bh0, bh1);
                        MMA_16816(acc[mt][n1][0], acc[mt][n1][1], acc[mt][n1][2], acc[mt][n1][3],
                                  ah[mt][0], ah[mt][1], ah[mt][2], ah[mt][3], bh2, bh3);
                        MMA_16816(acc[mt][n1][0], acc[mt][n1][1], acc[mt][n1][2], acc[mt][n1][3],
                                  ah[mt][0], ah[mt][1], ah[mt][2], ah[mt][3], bl2, bl3);
                        MMA_16816(acc[mt][n1][0], acc[mt][n1][1], acc[mt][n1][2], acc[mt][n1][3],
                                  al[mt][0], al[mt][1], al[mt][2], al[mt][3], bh2, bh3);
                    }
                }
            }
        }
        __syncthreads();
    }

    // ---------------- Phase 2: register softmax ----------------
    const float scale = 0.03125f;   // 1/sqrt(1024)
#pragma unroll
    for (int mt = 0; mt < 4; ++mt) {
#pragma unroll
        for (int half = 0; half < 2; ++half) {
            const int row = wm * 64 + mt * 16 + half * 8 + (lane >> 2);
            float m = -1e30f;
#pragma unroll
            for (int nt = 0; nt < 8; ++nt) {
#pragma unroll
                for (int j = 0; j < 2; ++j) {
                    const int col = wn * 64 + nt * 8 + (lane & 3) * 2 + j;
                    const bool ok = (col > row) && (col <= row + SPAN) &&
                                    (nblk > 0 || col >= SPAN);
                    float s = ok ? acc[mt][nt][half * 2 + j] * scale : -1e30f;
                    acc[mt][nt][half * 2 + j] = s;
                    m = fmaxf(m, s);
                }
            }
            m = fmaxf(m, __shfl_xor_sync(0xFFFFFFFFu, m, 1));
            m = fmaxf(m, __shfl_xor_sync(0xFFFFFFFFu, m, 2));
            if ((lane & 3) == 0) redmax[row][wn] = m;
        }
    }
    __syncthreads();
#pragma unroll
    for (int mt = 0; mt < 4; ++mt) {
#pragma unroll
        for (int half = 0; half < 2; ++half) {
            const int row = wm * 64 + mt * 16 + half * 8 + (lane >> 2);
            float m = fmaxf(fmaxf(redmax[row][0], redmax[row][1]),
                            fmaxf(redmax[row][2], redmax[row][3]));
            float sum = 0.0f;
#pragma unroll
            for (int nt = 0; nt < 8; ++nt) {
#pragma unroll
                for (int j = 0; j < 2; ++j) {
                    float s = acc[mt][nt][half * 2 + j];
                    float p = (s > -1e29f) ? __expf(s - m) : 0.0f;
                    acc[mt][nt][half * 2 + j] = p;
                    sum += p;
                }
            }
            sum += __shfl_xor_sync(0xFFFFFFFFu, sum, 1);
            sum += __shfl_xor_sync(0xFFFFFFFFu, sum, 2);
            if ((lane & 3) == 0) redsum[row][wn] = sum;
        }
    }
    __syncthreads();
    // Write P (bf16 hi/lo) to smem with 512B-row swizzle
#pragma unroll
    for (int mt = 0; mt < 4; ++mt) {
#pragma unroll
        for (int half = 0; half < 2; ++half) {
            const int row = wm * 64 + mt * 16 + half * 8 + (lane >> 2);
            const float inv = 1.0f / (redsum[row][0] + redsum[row][1] +
                                      redsum[row][2] + redsum[row][3]);
#pragma unroll
            for (int nt = 0; nt < 8; ++nt) {
                const int col = wn * 64 + nt * 8 + (lane & 3) * 2;
                float p0 = acc[mt][nt][half * 2 + 0] * inv;
                float p1 = acc[mt][nt][half * 2 + 1] * inv;
                ushort2 h, l;
                bfsplit(p0, h.x, l.x);
                bfsplit(p1, h.y, l.y);
                uint32_t off = (uint32_t)(row * 512 + col * 2);
                off ^= (off >> 5) & 0x70;
                asm volatile("st.shared.b32 [%0], %1;"
                             :: "r"(smem + P_H + off), "r"(*(uint32_t*)&h) : "memory");
                asm volatile("st.shared.b32 [%0], %1;"
                             :: "r"(smem + P_L + off), "r"(*(uint32_t*)&l) : "memory");
            }
        }
    }
    __syncthreads();

    // ---------------- Phase 3: O = P @ V (3-term split) ----------------
    auto load_v = [&](int kc, int buf, int d0) {
        const uint32_t sb = smem + V_BASE + buf * 32768u;
#pragma unroll
        for (int i = 0; i < 4; ++i) {
            int idx = tid + i * 256;
            int r = idx >> 5, ch = idx & 31;
            int vrow = kv0 + kc * 32 + r; if (vrow < 0) vrow = 0;
            uint32_t dst = (uint32_t)(r * 512 + ((ch ^ (r & 7)) * 16));
            const size_t goff = ((size_t)b * TT + vrow) * DD + d0 + ch * 8;
            CP_ASYNC_16(sb + dst, a.vh + goff);
            CP_ASYNC_16(sb + 16384u + dst, a.vl + goff);
        }
        CP_ASYNC_COMMIT();
    };

    for (int dc = 0; dc < 4; ++dc) {
        const int d0 = dc * 256;
        float acc2[4][8][4];
#pragma unroll
        for (int mt = 0; mt < 4; ++mt)
#pragma unroll
            for (int nt = 0; nt < 8; ++nt)
#pragma unroll
                for (int j = 0; j < 4; ++j) acc2[mt][nt][j] = 0.0f;

        load_v(0, 0, d0);
        for (int kc = 0; kc < 8; ++kc) {
            const int buf = kc & 1;
            if (kc + 1 < 8) {
                load_v(kc + 1, (kc + 1) & 1, d0);
                CP_ASYNC_WAIT(1);
            } else {
                CP_ASYNC_WAIT(0);
            }
            __syncthreads();

            // Keys in this chunk multiply all-zero P rows for this warp?
            const bool pskip = ((kc * 32 + 31) <= (wm * 64)) ||
                               ((kc * 32) > (wm * 64 + 191)) ||
                               (nblk == 0 && kc < 4);
            if (!pskip) {
                const uint32_t vb = smem + V_BASE + buf * 32768u;
#pragma unroll
                for (int ks = 0; ks < 2; ++ks) {
                    const int kbase = kc * 32 + ks * 16;
                    uint32_t ph[4][4], pl[4][4];
#pragma unroll
                    for (int mt = 0; mt < 4; ++mt) {
                        const int prow = wm * 64 + mt * 16 + (lane & 15);
                        uint32_t aoff = (uint32_t)(prow * 512 + kbase * 2 + (lane >> 4) * 16);
                        aoff ^= (aoff >> 5) & 0x70;
                        LDMATRIX_X4(ph[mt][0], ph[mt][1], ph[mt][2], ph[mt][3], smem + P_H + aoff);
                        LDMATRIX_X4(pl[mt][0], pl[mt][1], pl[mt][2], pl[mt][3], smem + P_L + aoff);
                    }
#pragma unroll
                    for (int ntp = 0; ntp < 4; ++ntp) {
                        const int vrow = ks * 16 + (lane & 15);
                        const int vcol = wn * 64 + ntp * 16 + ((lane >> 4) << 3);
                        uint32_t boff = (uint32_t)(vrow * 512 + vcol * 2);
                        boff ^= (boff >> 5) & 0x70;
                        uint32_t vh0, vh1, vh2, vh3, vl0, vl1, vl2, vl3;
                        LDMATRIX_X4T(vh0, vh1, vh2, vh3, vb + boff);
                        LDMATRIX_X4T(vl0, vl1, vl2, vl3, vb + 16384u + boff);
                        const int n0 = ntp * 2, n1 = ntp * 2 + 1;
#pragma unroll
                        for (int mt = 0; mt < 4; ++mt) {
                            MMA_16816(acc2[mt][n0][0], acc2[mt][n0][1], acc2[mt][n0][2], acc2[mt][n0][3],
                                      ph[mt][0], ph[mt][1], ph[mt][2], ph[mt][3], vh0, vh1);
                            MMA_16816(acc2[mt][n0][0], acc2[mt][n0][1], acc2[mt][n0][2], acc2[mt][n0][3],
                                      ph[mt][0], ph[mt][1], ph[mt][2], ph[mt][3], vl0, vl1);
                            MMA_16816(acc2[mt][n0][0], acc2[mt][n0][1], acc2[mt][n0][2], acc2[mt][n0][3],
                                      pl[mt][0], pl[mt][1], pl[mt][2], pl[mt][3], vh0, vh1);
                            MMA_16816(acc2[mt][n1][0], acc2[mt][n1][1], acc2[mt][n1][2], acc2[mt][n1][3],
                                      ph[mt][0], ph[mt][1], ph[mt][2], ph[mt][3], vh2, vh3);
                            MMA_16816(acc2[mt][n1][0], acc2[mt][n1][1], acc2[mt][n1][2], acc2[mt][n1][3],
                                      ph[mt][0], ph[mt][1], ph[mt][2], ph[mt][3], vl2, vl3);
                            MMA_16816(acc2[mt][n1][0], acc2[mt][n1][1], acc2[mt][n1][2], acc2[mt][n1][3],
                                      pl[mt][0], pl[mt][1], pl[mt][2], pl[mt][3], vh2, vh3);
                        }
                    }
                }
            }
            __syncthreads();
        }

        // Epilogue for this d-chunk
#pragma unroll
        for (int mt = 0; mt < 4; ++mt) {
#pragma unroll
            for (int nt = 0; nt < 8; ++nt) {
                const size_t row = qrow0 + wm * 64 + mt * 16 + (lane >> 2);
                const int col = d0 + wn * 64 + nt * 8 + (lane & 3) * 2;
                float2 v0 = make_float2(acc2[mt][nt][0], acc2[mt][nt][1]);
                float2 v1 = make_float2(acc2[mt][nt][2], acc2[mt][nt][3]);
                *reinterpret_cast<float2*>(a.out + row * DD + col) = v0;
                *reinterpret_cast<float2*>(a.out + (row + 8) * DD + col) = v1;
            }
        }
    }
}

// ---------------------------------------------------------------------------
extern "C" void kernel_launch(void* const* d_in, const int* in_sizes, int n_in,
                              void* d_out, int out_size) {
    const float* x  = (const float*)d_in[0];
    const float* Wq = (const float*)d_in[1];
    const float* bq = (const float*)d_in[2];
    const float* Wk = (const float*)d_in[3];
    const float* bk = (const float*)d_in[4];
    const float* Wv = (const float*)d_in[5];
    const float* bv = (const float*)d_in[6];
    float* out = (float*)d_out;

    ushortx *xh, *xl, *wh, *wl, *qh, *ql, *kh, *kl, *vh, *vl;
    cudaGetSymbolAddress((void**)&xh, g_xh);
    cudaGetSymbolAddress((void**)&xl, g_xl);
    cudaGetSymbolAddress((void**)&wh, g_wh);
    cudaGetSymbolAddress((void**)&wl, g_wl);
    cudaGetSymbolAddress((void**)&qh, g_qh);
    cudaGetSymbolAddress((void**)&ql, g_ql);
    cudaGetSymbolAddress((void**)&kh, g_kh);
    cudaGetSymbolAddress((void**)&kl, g_kl);
    cudaGetSymbolAddress((void**)&vh, g_vh);
    cudaGetSymbolAddress((void**)&vl, g_vl);

    // Split fp32 -> bf16 hi/lo
    {
        int n4 = MROWS * DD / 4;
        split_bf16<<<(n4 + 255) / 256, 256>>>(x, xh, xl, n4);
        int w4 = DD * DD / 4;
        split_bf16<<<(w4 + 255) / 256, 256>>>(Wq, wh + 0 * (size_t)DD * DD, wl + 0 * (size_t)DD * DD, w4);
        split_bf16<<<(w4 + 255) / 256, 256>>>(Wk, wh + 1 * (size_t)DD * DD, wl + 1 * (size_t)DD * DD, w4);
        split_bf16<<<(w4 + 255) / 256, 256>>>(Wv, wh + 2 * (size_t)DD * DD, wl + 2 * (size_t)DD * DD, w4);
    }

    GemmArgs ga;
    ga.xh = xh; ga.xl = xl;
    ga.wh[0] = wh;                       ga.wl[0] = wl;
    ga.wh[1] = wh + 1 * (size_t)DD * DD; ga.wl[1] = wl + 1 * (size_t)DD * DD;
    ga.wh[2] = wh + 2 * (size_t)DD * DD; ga.wl[2] = wl + 2 * (size_t)DD * DD;
    ga.bias[0] = bq; ga.bias[1] = bk; ga.bias[2] = bv;
    ga.outh[0] = qh; ga.outl[0] = ql;
    ga.outh[1] = kh; ga.outl[1] = kl;
    ga.outh[2] = vh; ga.outl[2] = vl;

    cudaFuncSetAttribute(qkv_tc_gemm, cudaFuncAttributeMaxDynamicSharedMemorySize,
                         GEMM_DSMEM);
    qkv_tc_gemm<<<dim3(DD / 128, MROWS / 128, 3), 256, GEMM_DSMEM>>>(ga);

    AttnArgs aa;
    aa.qh = qh; aa.ql = ql; aa.kh = kh; aa.kl = kl; aa.vh = vh; aa.vl = vl;
    aa.out = out;
    cudaFuncSetAttribute(attn_tc, cudaFuncAttributeMaxDynamicSharedMemorySize,
                         ATTN_DSMEM);
    attn_tc<<<dim3(NB, BB), 256, ATTN_DSMEM>>>(aa);
}

// round 9
// speedup vs baseline: 3.1780x; 1.0076x over previous
#include <cuda_runtime.h>
#include <cuda_bf16.h>
#include <math.h>
#include <stdint.h>

// Problem constants (fixed shapes)
#define BB 4
#define TT 4096
#define DD 1024
#define SPAN 128
#define NB (TT / SPAN)      // 32
#define MROWS (BB * TT)     // 16384

typedef unsigned short ushortx;

// Scratch (device globals: no allocation APIs allowed)
__device__ ushortx g_xh[(size_t)MROWS * DD];
__device__ ushortx g_xl[(size_t)MROWS * DD];
__device__ ushortx g_wh[(size_t)3 * DD * DD];
__device__ ushortx g_wl[(size_t)3 * DD * DD];
__device__ ushortx g_qh[(size_t)MROWS * DD];
__device__ ushortx g_ql[(size_t)MROWS * DD];
__device__ ushortx g_kh[(size_t)MROWS * DD];
__device__ ushortx g_kl[(size_t)MROWS * DD];
__device__ ushortx g_vh[(size_t)MROWS * DD];
__device__ ushortx g_vl[(size_t)MROWS * DD];

__device__ __forceinline__ uint32_t smem_u32(const void* p) {
    uint32_t a;
    asm("{ .reg .u64 t; cvta.to.shared.u64 t, %1; cvt.u32.u64 %0, t; }"
        : "=r"(a) : "l"(p));
    return a;
}

#define LDMATRIX_X4(r0, r1, r2, r3, addr) \
    asm volatile("ldmatrix.sync.aligned.m8n8.x4.shared.b16 {%0,%1,%2,%3}, [%4];" \
                 : "=r"(r0), "=r"(r1), "=r"(r2), "=r"(r3) : "r"(addr))
#define LDMATRIX_X4T(r0, r1, r2, r3, addr) \
    asm volatile("ldmatrix.sync.aligned.m8n8.x4.trans.shared.b16 {%0,%1,%2,%3}, [%4];" \
                 : "=r"(r0), "=r"(r1), "=r"(r2), "=r"(r3) : "r"(addr))
#define MMA_16816(c0, c1, c2, c3, a0, a1, a2, a3, b0, b1) \
    asm volatile("mma.sync.aligned.m16n8k16.row.col.f32.bf16.bf16.f32 " \
                 "{%0,%1,%2,%3}, {%4,%5,%6,%7}, {%8,%9}, {%0,%1,%2,%3};" \
                 : "+f"(c0), "+f"(c1), "+f"(c2), "+f"(c3) \
                 : "r"(a0), "r"(a1), "r"(a2), "r"(a3), "r"(b0), "r"(b1))
#define CP_ASYNC_16(dst, src) \
    asm volatile("cp.async.cg.shared.global [%0], [%1], 16;" \
                 :: "r"(dst), "l"(src) : "memory")
#define CP_ASYNC_COMMIT() asm volatile("cp.async.commit_group;" ::: "memory")
#define CP_ASYNC_WAIT(n)  asm volatile("cp.async.wait_group %0;" :: "n"(n) : "memory")

__device__ __forceinline__ void bfsplit(float v, ushortx& h, ushortx& l) {
    __nv_bfloat16 hb = __float2bfloat16(v);
    __nv_bfloat16 lb = __float2bfloat16(v - __bfloat162float(hb));
    h = __bfloat16_as_ushort(hb);
    l = __bfloat16_as_ushort(lb);
}

// ---------------------------------------------------------------------------
// Split fp32 -> bf16 hi + bf16 lo
// ---------------------------------------------------------------------------
__global__ __launch_bounds__(256) void split_bf16(const float* __restrict__ src,
                                                  ushortx* __restrict__ hi,
                                                  ushortx* __restrict__ lo,
                                                  int n4) {
    int i = blockIdx.x * 256 + threadIdx.x;
    if (i >= n4) return;
    float4 v = reinterpret_cast<const float4*>(src)[i];
    ushort4 hv, lv;
    bfsplit(v.x, hv.x, lv.x);
    bfsplit(v.y, hv.y, lv.y);
    bfsplit(v.z, hv.z, lv.z);
    bfsplit(v.w, hv.w, lv.w);
    reinterpret_cast<ushort4*>(hi)[i] = hv;
    reinterpret_cast<ushort4*>(lo)[i] = lv;
}

// ---------------------------------------------------------------------------
// Split-bf16 tensor-core GEMM: 512 threads, CTA tile M=256 x N=128,
// 16 warps (4 m x 4 n), warp tile 64x32, K-chunk 64, 2-stage cp.async.
// out = x @ W^T + bias, emitted as bf16 hi/lo pairs.
// ---------------------------------------------------------------------------
struct GemmArgs {
    const ushortx* xh;
    const ushortx* xl;
    const ushortx* wh[3];
    const ushortx* wl[3];
    const float* bias[3];
    ushortx* outh[3];
    ushortx* outl[3];
};

#define NUM_CHUNKS (DD / 64)     // 16
// Stage layout (per 64-wide K chunk): Ah 32K | Al 32K | Bh 16K | Bl 16K
#define G_AH 0u
#define G_AL 32768u
#define G_BH 65536u
#define G_BL 81920u
#define G_STAGE 98304u
#define GEMM_DSMEM (2u * G_STAGE)   // 192 KB

__global__ __launch_bounds__(512) void qkv_tc_gemm(GemmArgs args) {
    extern __shared__ char dsm[];
    const int tid = threadIdx.x;
    const int wid = tid >> 5;
    const int lane = tid & 31;
    const int bn = blockIdx.x * 128;
    const int bm = blockIdx.y * 256;
    const int z  = blockIdx.z;
    const int warp_m = wid >> 2;     // 0..3 -> rows 64*warp_m
    const int warp_n = wid & 3;      // 0..3 -> cols 32*warp_n

    const uint32_t smem_base = smem_u32(dsm);

    const ushortx* Ah = args.xh    + (size_t)bm * DD;
    const ushortx* Al = args.xl    + (size_t)bm * DD;
    const ushortx* Bh = args.wh[z] + (size_t)bn * DD;
    const ushortx* Bl = args.wl[z] + (size_t)bn * DD;

    auto load_stage = [&](int c, int buf) {
        const int k0 = c * 64;
        const uint32_t sb = smem_base + buf * G_STAGE;
        // A: 256 rows x 8 chunks x 2 tiles; 4 cp.async per tile per thread
#pragma unroll
        for (int i = 0; i < 4; ++i) {
            int idx = tid + i * 512;
            int r = idx >> 3, ch = idx & 7;
            uint32_t dst = (uint32_t)(r * 128 + ((ch ^ (r & 7)) * 16));
            const size_t go = (size_t)r * DD + k0 + ch * 8;
            CP_ASYNC_16(sb + G_AH + dst, Ah + go);
            CP_ASYNC_16(sb + G_AL + dst, Al + go);
        }
        // B: 128 rows x 8 chunks x 2 tiles; 2 cp.async per tile per thread
#pragma unroll
        for (int i = 0; i < 2; ++i) {
            int idx = tid + i * 512;
            int r = idx >> 3, ch = idx & 7;
            uint32_t dst = (uint32_t)(r * 128 + ((ch ^ (r & 7)) * 16));
            const size_t go = (size_t)r * DD + k0 + ch * 8;
            CP_ASYNC_16(sb + G_BH + dst, Bh + go);
            CP_ASYNC_16(sb + G_BL + dst, Bl + go);
        }
        CP_ASYNC_COMMIT();
    };

    float acc[4][4][4];
#pragma unroll
    for (int mt = 0; mt < 4; ++mt)
#pragma unroll
        for (int nt = 0; nt < 4; ++nt)
#pragma unroll
            for (int j = 0; j < 4; ++j) acc[mt][nt][j] = 0.0f;

    // A (x4): row = warpm*64 + mt*16 + (lane&15), koff = (lane>>4)*16
    const int a_row = warp_m * 64 + (lane & 15);
    const uint32_t a_sw = (uint32_t)((a_row & 7) * 16);
    const uint32_t a_kb_lane = (uint32_t)((lane >> 4) * 16);
    // B (x4, 16 n-rows per load)
    const int b_row2 = warp_n * 32 + (lane & 7) + ((lane >> 4) << 3);
    const uint32_t b_koff = (uint32_t)(((lane >> 3) & 1) * 16);
    const uint32_t b_sw2 = (uint32_t)((lane & 7) * 16);

    load_stage(0, 0);

    for (int c = 0; c < NUM_CHUNKS; ++c) {
        const int buf = c & 1;
        CP_ASYNC_WAIT(0);
        __syncthreads();
        if (c + 1 < NUM_CHUNKS) load_stage(c + 1, buf ^ 1);

        const uint32_t sb = smem_base + buf * G_STAGE;
        const uint32_t a_base_h = sb + G_AH + a_row * 128;
        const uint32_t a_base_l = sb + G_AL + a_row * 128;
        const uint32_t b_tile_h = sb + G_BH;
        const uint32_t b_tile_l = sb + G_BL;

#pragma unroll
        for (int ks = 0; ks < 4; ++ks) {
            const uint32_t akb = (uint32_t)(ks * 32) + a_kb_lane;
            uint32_t ah[4][4], al[4][4];
#pragma unroll
            for (int mt = 0; mt < 4; ++mt) {
                const uint32_t moff = (uint32_t)(mt * 16 * 128);
                LDMATRIX_X4(ah[mt][0], ah[mt][1], ah[mt][2], ah[mt][3],
                            a_base_h + moff + (akb ^ a_sw));
                LDMATRIX_X4(al[mt][0], al[mt][1], al[mt][2], al[mt][3],
                            a_base_l + moff + (akb ^ a_sw));
            }
#pragma unroll
            for (int ntp = 0; ntp < 2; ++ntp) {
                const uint32_t ba = (uint32_t)((b_row2 + ntp * 16) * 128) +
                                    (((uint32_t)(ks * 32) + b_koff) ^ b_sw2);
                uint32_t bh0, bh1, bh2, bh3, bl0, bl1, bl2, bl3;
                LDMATRIX_X4(bh0, bh1, bh2, bh3, b_tile_h + ba);
                LDMATRIX_X4(bl0, bl1, bl2, bl3, b_tile_l + ba);
                const int n0 = ntp * 2, n1 = ntp * 2 + 1;
#pragma unroll
                for (int mt = 0; mt < 4; ++mt) {
                    MMA_16816(acc[mt][n0][0], acc[mt][n0][1], acc[mt][n0][2], acc[mt][n0][3],
                              ah[mt][0], ah[mt][1], ah[mt][2], ah[mt][3], bh0, bh1);
                    MMA_16816(acc[mt][n0][0], acc[mt][n0][1], acc[mt][n0][2], acc[mt][n0][3],
                              ah[mt][0], ah[mt][1], ah[mt][2], ah[mt][3], bl0, bl1);
                    MMA_16816(acc[mt][n0][0], acc[mt][n0][1], acc[mt][n0][2], acc[mt][n0][3],
                              al[mt][0], al[mt][1], al[mt][2], al[mt][3], bh0, bh1);
                    MMA_16816(acc[mt][n1][0], acc[mt][n1][1], acc[mt][n1][2], acc[mt][n1][3],
                              ah[mt][0], ah[mt][1], ah[mt][2], ah[mt][3], bh2, bh3);
                    MMA_16816(acc[mt][n1][0], acc[mt][n1][1], acc[mt][n1][2], acc[mt][n1][3],
                              ah[mt][0], ah[mt][1], ah[mt][2], ah[mt][3], bl2, bl3);
                    MMA_16816(acc[mt][n1][0], acc[mt][n1][1], acc[mt][n1][2], acc[mt][n1][3],
                              al[mt][0], al[mt][1], al[mt][2], al[mt][3], bh2, bh3);
                }
            }
        }
        __syncthreads();
    }

    // Epilogue: add bias, split to bf16 hi/lo, store
    const float* bias = args.bias[z];
    ushortx* outh = args.outh[z];
    ushortx* outl = args.outl[z];
    const int er = bm + warp_m * 64 + (lane >> 2);
    const int ec = bn + warp_n * 32 + (lane & 3) * 2;
#pragma unroll
    for (int mt = 0; mt < 4; ++mt) {
#pragma unroll
        for (int nt = 0; nt < 4; ++nt) {
            const int r0 = er + mt * 16;
            const int cc = ec + nt * 8;
            float v0 = acc[mt][nt][0] + bias[cc];
            float v1 = acc[mt][nt][1] + bias[cc + 1];
            float v2 = acc[mt][nt][2] + bias[cc];
            float v3 = acc[mt][nt][3] + bias[cc + 1];
            ushort2 h01, l01, h23, l23;
            bfsplit(v0, h01.x, l01.x); bfsplit(v1, h01.y, l01.y);
            bfsplit(v2, h23.x, l23.x); bfsplit(v3, h23.y, l23.y);
            *reinterpret_cast<ushort2*>(outh + (size_t)r0 * DD + cc) = h01;
            *reinterpret_cast<ushort2*>(outl + (size_t)r0 * DD + cc) = l01;
            *reinterpret_cast<ushort2*>(outh + (size_t)(r0 + 8) * DD + cc) = h23;
            *reinterpret_cast<ushort2*>(outl + (size_t)(r0 + 8) * DD + cc) = l23;
        }
    }
}

// ---------------------------------------------------------------------------
// Tensor-core windowed attention with masked-tile skipping.
// One CTA per (b, n): 128 q rows x 256 keys. 8 warps (2 m x 4 n).
// ---------------------------------------------------------------------------
struct AttnArgs {
    const ushortx *qh, *ql, *kh, *kl, *vh, *vl;
    float* out;
};

#define A_STAGE 98304u             // Qh 16K | Ql 16K | Kh 32K | Kl 32K
#define A_QH 0u
#define A_QL 16384u
#define A_KH 32768u
#define A_KL 65536u
#define P_H  0u
#define P_L  65536u
#define V_BASE 131072u
#define ATTN_DSMEM 196608u

__global__ __launch_bounds__(256) void attn_tc(AttnArgs a) {
    extern __shared__ char dsm[];
    __shared__ float redmax[128][4];
    __shared__ float redsum[128][4];

    const int tid = threadIdx.x;
    const int wid = tid >> 5;
    const int lane = tid & 31;
    const int wm = wid >> 2;
    const int wn = wid & 3;
    const int nblk = blockIdx.x;
    const int b = blockIdx.y;
    const size_t qrow0 = (size_t)b * TT + (size_t)nblk * SPAN;
    const int kv0 = (nblk - 1) * SPAN;
    const uint32_t smem = smem_u32(dsm);

    const bool s1skip = ((wn * 64 + 63) <= (wm * 64)) ||
                        ((wn * 64) > (wm * 64 + 191)) ||
                        (nblk == 0 && wn < 2);

    float acc[4][8][4];
#pragma unroll
    for (int mt = 0; mt < 4; ++mt)
#pragma unroll
        for (int nt = 0; nt < 8; ++nt)
#pragma unroll
            for (int j = 0; j < 4; ++j) acc[mt][nt][j] = 0.0f;

    auto load_stage1 = [&](int c, int buf) {
        const int k0 = c * 64;
        const uint32_t sb = smem + buf * A_STAGE;
#pragma unroll
        for (int i = 0; i < 4; ++i) {
            int idx = tid + i * 256;
            int r = idx >> 3, ch = idx & 7;
            uint32_t dst = (uint32_t)(r * 128 + ((ch ^ (r & 7)) * 16));
            const size_t goff = (qrow0 + r) * DD + k0 + ch * 8;
            CP_ASYNC_16(sb + A_QH + dst, a.qh + goff);
            CP_ASYNC_16(sb + A_QL + dst, a.ql + goff);
        }
#pragma unroll
        for (int i = 0; i < 8; ++i) {
            int idx = tid + i * 256;
            int r = idx >> 3, ch = idx & 7;
            int krow = kv0 + r; if (krow < 0) krow = 0;
            uint32_t dst = (uint32_t)(r * 128 + ((ch ^ (r & 7)) * 16));
            const size_t goff = ((size_t)b * TT + krow) * DD + k0 + ch * 8;
            CP_ASYNC_16(sb + A_KH + dst, a.kh + goff);
            CP_ASYNC_16(sb + A_KL + dst, a.kl + goff);
        }
        CP_ASYNC_COMMIT();
    };

    const int a_row = wm * 64 + (lane & 15);
    const uint32_t a_sw = (uint32_t)((a_row & 7) * 16);
    const uint32_t a_kb_lane = (uint32_t)((lane >> 4) * 16);
    const int b_row2 = wn * 64 + (lane & 7) + ((lane >> 4) << 3);
    const uint32_t b_koff = (uint32_t)(((lane >> 3) & 1) * 16);
    const uint32_t b_sw2 = (uint32_t)((lane & 7) * 16);

    load_stage1(0, 0);

    for (int c = 0; c < NUM_CHUNKS; ++c) {
        const int buf = c & 1;
        if (c + 1 < NUM_CHUNKS) {
            load_stage1(c + 1, (c + 1) & 1);
            CP_ASYNC_WAIT(1);
        } else {
            CP_ASYNC_WAIT(0);
        }
        __syncthreads();

        if (!s1skip) {
            const uint32_t sb = smem + buf * A_STAGE;
            const uint32_t a_base_h = sb + A_QH + a_row * 128;
            const uint32_t a_base_l = sb + A_QL + a_row * 128;

#pragma unroll
            for (int ks = 0; ks < 4; ++ks) {
                const uint32_t akb = (uint32_t)(ks * 32) + a_kb_lane;
                uint32_t ah[4][4], al[4][4];
#pragma unroll
                for (int mt = 0; mt < 4; ++mt) {
                    const uint32_t moff = (uint32_t)(mt * 16 * 128);
                    LDMATRIX_X4(ah[mt][0], ah[mt][1], ah[mt][2], ah[mt][3],
                                a_base_h + moff + (akb ^ a_sw));
                    LDMATRIX_X4(al[mt][0], al[mt][1], al[mt][2], al[mt][3],
                                a_base_l + moff + (akb ^ a_sw));
                }
#pragma unroll
                for (int ntp = 0; ntp < 4; ++ntp) {
                    const uint32_t ba = (uint32_t)((b_row2 + ntp * 16) * 128) +
                                        (((uint32_t)(ks * 32) + b_koff) ^ b_sw2);
                    uint32_t bh0, bh1, bh2, bh3, bl0, bl1, bl2, bl3;
                    LDMATRIX_X4(bh0, bh1, bh2, bh3, sb + A_KH + ba);
                    LDMATRIX_X4(bl0, bl1, bl2, bl3, sb + A_KL + ba);
                    const int n0 = ntp * 2, n1 = ntp * 2 + 1;
#pragma unroll
                    for (int mt = 0; mt < 4; ++mt) {
                        MMA_16816(acc[mt][n0][0], acc[mt][n0][1], acc[mt][n0][2], acc[mt][n0][3],
                                  ah[mt][0], ah[mt][1], ah[mt][2], ah[mt][3], bh0, bh1);
                        MMA_16816(acc[mt][n0][0], acc[mt][n0][1], acc[mt][n0][2], acc[mt][n0][3],
                                  ah[mt][0], ah[mt][1], ah[mt][2], ah[mt][3], bl0, bl1);
                        MMA_16816(acc[mt][n0][0], acc[mt][n0][1], acc[mt][n0][2], acc[mt][n0][3],
                                  al[mt][0], al[mt][1], al[mt][2], al[mt][3], bh0, bh1);
                        MMA_16816(acc[mt][n1][0], acc[mt][n1][1], acc[mt][n1][2], acc[mt][n1][3],
                                  ah[mt][0], ah[mt][1], ah[mt][2], ah[mt][3], bh2, bh3);
                        MMA_16816(acc[mt][n1][0], acc[mt][n1][1], acc[mt][n1][2], acc[mt][n1][3],
                                  ah[mt][0], ah[mt][1], ah[mt][2], ah[mt][3], bl2, bl3);
                        MMA_16816(acc[mt][n1][0], acc[mt][n1][1], acc[mt][n1][2], acc[mt][n1][3],
                                  al[mt][0], al[mt][1], al[mt][2], al[mt][3], bh2, bh3);
                    }
                }
            }
        }
        __syncthreads();
    }

    const float scale = 0.03125f;
#pragma unroll
    for (int mt = 0; mt < 4; ++mt) {
#pragma unroll
        for (int half = 0; half < 2; ++half) {
            const int row = wm * 64 + mt * 16 + half * 8 + (lane >> 2);
            float m = -1e30f;
#pragma unroll
            for (int nt = 0; nt < 8; ++nt) {
#pragma unroll
                for (int j = 0; j < 2; ++j) {
                    const int col = wn * 64 + nt * 8 + (lane & 3) * 2 + j;
                    const bool ok = (col > row) && (col <= row + SPAN) &&
                                    (nblk > 0 || col >= SPAN);
                    float s = ok ? acc[mt][nt][half * 2 + j] * scale : -1e30f;
                    acc[mt][nt][half * 2 + j] = s;
                    m = fmaxf(m, s);
                }
            }
            m = fmaxf(m, __shfl_xor_sync(0xFFFFFFFFu, m, 1));
            m = fmaxf(m, __shfl_xor_sync(0xFFFFFFFFu, m, 2));
            if ((lane & 3) == 0) redmax[row][wn] = m;
        }
    }
    __syncthreads();
#pragma unroll
    for (int mt = 0; mt < 4; ++mt) {
#pragma unroll
        for (int half = 0; half < 2; ++half) {
            const int row = wm * 64 + mt * 16 + half * 8 + (lane >> 2);
            float m = fmaxf(fmaxf(redmax[row][0], redmax[row][1]),
                            fmaxf(redmax[row][2], redmax[row][3]));
            float sum = 0.0f;
#pragma unroll
            for (int nt = 0; nt < 8; ++nt) {
#pragma unroll
                for (int j = 0; j < 2; ++j) {
                    float s = acc[mt][nt][half * 2 + j];
                    float p = (s > -1e29f) ? __expf(s - m) : 0.0f;
                    acc[mt][nt][half * 2 + j] = p;
                    sum += p;
                }
            }
            sum += __shfl_xor_sync(0xFFFFFFFFu, sum, 1);
            sum += __shfl_xor_sync(0xFFFFFFFFu, sum, 2);
            if ((lane & 3) == 0) redsum[row][wn] = sum;
        }
    }
    __syncthreads();
#pragma unroll
    for (int mt = 0; mt < 4; ++mt) {
#pragma unroll
        for (int half = 0; half < 2; ++half) {
            const int row = wm * 64 + mt * 16 + half * 8 + (lane >> 2);
            const float inv = 1.0f / (redsum[row][0] + redsum[row][1] +
                                      redsum[row][2] + redsum[row][3]);
#pragma unroll
            for (int nt = 0; nt < 8; ++nt) {
                const int col = wn * 64 + nt * 8 + (lane & 3) * 2;
                float p0 = acc[mt][nt][half * 2 + 0] * inv;
                float p1 = acc[mt][nt][half * 2 + 1] * inv;
                ushort2 h, l;
                bfsplit(p0, h.x, l.x);
                bfsplit(p1, h.y, l.y);
                uint32_t off = (uint32_t)(row * 512 + col * 2);
                off ^= (off >> 5) & 0x70;
                asm volatile("st.shared.b32 [%0], %1;"
                             :: "r"(smem + P_H + off), "r"(*(uint32_t*)&h) : "memory");
                asm volatile("st.shared.b32 [%0], %1;"
                             :: "r"(smem + P_L + off), "r"(*(uint32_t*)&l) : "memory");
            }
        }
    }
    __syncthreads();

    auto load_v = [&](int kc, int buf, int d0) {
        const uint32_t sb = smem + V_BASE + buf * 32768u;
#pragma unroll
        for (int i = 0; i < 4; ++i) {
            int idx = tid + i * 256;
            int r = idx >> 5, ch = idx & 31;
            int vrow = kv0 + kc * 32 + r; if (vrow < 0) vrow = 0;
            uint32_t dst = (uint32_t)(r * 512 + ((ch ^ (r & 7)) * 16));
            const size_t goff = ((size_t)b * TT + vrow) * DD + d0 + ch * 8;
            CP_ASYNC_16(sb + dst, a.vh + goff);
            CP_ASYNC_16(sb + 16384u + dst, a.vl + goff);
        }
        CP_ASYNC_COMMIT();
    };

    for (int dc = 0; dc < 4; ++dc) {
        const int d0 = dc * 256;
        float acc2[4][8][4];
#pragma unroll
        for (int mt = 0; mt < 4; ++mt)
#pragma unroll
            for (int nt = 0; nt < 8; ++nt)
#pragma unroll
                for (int j = 0; j < 4; ++j) acc2[mt][nt][j] = 0.0f;

        load_v(0, 0, d0);
        for (int kc = 0; kc < 8; ++kc) {
            const int buf = kc & 1;
            if (kc + 1 < 8) {
                load_v(kc + 1, (kc + 1) & 1, d0);
                CP_ASYNC_WAIT(1);
            } else {
                CP_ASYNC_WAIT(0);
            }
            __syncthreads();

            const bool pskip = ((kc * 32 + 31) <= (wm * 64)) ||
                               ((kc * 32) > (wm * 64 + 191)) ||
                               (nblk == 0 && kc < 4);
            if (!pskip) {
                const uint32_t vb = smem + V_BASE + buf * 32768u;
#pragma unroll
                for (int ks = 0; ks < 2; ++ks) {
                    const int kbase = kc * 32 + ks * 16;
                    uint32_t ph[4][4], pl[4][4];
#pragma unroll
                    for (int mt = 0; mt < 4; ++mt) {
                        const int prow = wm * 64 + mt * 16 + (lane & 15);
                        uint32_t aoff = (uint32_t)(prow * 512 + kbase * 2 + (lane >> 4) * 16);
                        aoff ^= (aoff >> 5) & 0x70;
                        LDMATRIX_X4(ph[mt][0], ph[mt][1], ph[mt][2], ph[mt][3], smem + P_H + aoff);
                        LDMATRIX_X4(pl[mt][0], pl[mt][1], pl[mt][2], pl[mt][3], smem + P_L + aoff);
                    }
#pragma unroll
                    for (int ntp = 0; ntp < 4; ++ntp) {
                        const int vrow = ks * 16 + (lane & 15);
                        const int vcol = wn * 64 + ntp * 16 + ((lane >> 4) << 3);
                        uint32_t boff = (uint32_t)(vrow * 512 + vcol * 2);
                        boff ^= (boff >> 5) & 0x70;
                        uint32_t vh0, vh1, vh2, vh3, vl0, vl1, vl2, vl3;
                        LDMATRIX_X4T(vh0, vh1, vh2, vh3, vb + boff);
                        LDMATRIX_X4T(vl0, vl1, vl2, vl3, vb + 16384u + boff);
                        const int n0 = ntp * 2, n1 = ntp * 2 + 1;
#pragma unroll
                        for (int mt = 0; mt < 4; ++mt) {
                            MMA_16816(acc2[mt][n0][0], acc2[mt][n0][1], acc2[mt][n0][2], acc2[mt][n0][3],
                                      ph[mt][0], ph[mt][1], ph[mt][2], ph[mt][3], vh0, vh1);
                            MMA_16816(acc2[mt][n0][0], acc2[mt][n0][1], acc2[mt][n0][2], acc2[mt][n0][3],
                                      ph[mt][0], ph[mt][1], ph[mt][2], ph[mt][3], vl0, vl1);
                            MMA_16816(acc2[mt][n0][0], acc2[mt][n0][1], acc2[mt][n0][2], acc2[mt][n0][3],
                                      pl[mt][0], pl[mt][1], pl[mt][2], pl[mt][3], vh0, vh1);
                            MMA_16816(acc2[mt][n1][0], acc2[mt][n1][1], acc2[mt][n1][2], acc2[mt][n1][3],
                                      ph[mt][0], ph[mt][1], ph[mt][2], ph[mt][3], vh2, vh3);
                            MMA_16816(acc2[mt][n1][0], acc2[mt][n1][1], acc2[mt][n1][2], acc2[mt][n1][3],
                                      ph[mt][0], ph[mt][1], ph[mt][2], ph[mt][3], vl2, vl3);
                            MMA_16816(acc2[mt][n1][0], acc2[mt][n1][1], acc2[mt][n1][2], acc2[mt][n1][3],
                                      pl[mt][0], pl[mt][1], pl[mt][2], pl[mt][3], vh2, vh3);
                        }
                    }
                }
            }
            __syncthreads();
        }

#pragma unroll
        for (int mt = 0; mt < 4; ++mt) {
#pragma unroll
            for (int nt = 0; nt < 8; ++nt) {
                const size_t row = qrow0 + wm * 64 + mt * 16 + (lane >> 2);
                const int col = d0 + wn * 64 + nt * 8 + (lane & 3) * 2;
                float2 v0 = make_float2(acc2[mt][nt][0], acc2[mt][nt][1]);
                float2 v1 = make_float2(acc2[mt][nt][2], acc2[mt][nt][3]);
                *reinterpret_cast<float2*>(a.out + row * DD + col) = v0;
                *reinterpret_cast<float2*>(a.out + (row + 8) * DD + col) = v1;
            }
        }
    }
}

// ---------------------------------------------------------------------------
extern "C" void kernel_launch(void* const* d_in, const int* in_sizes, int n_in,
                              void* d_out, int out_size) {
    const float* x  = (const float*)d_in[0];
    const float* Wq = (const float*)d_in[1];
    const float* bq = (const float*)d_in[2];
    const float* Wk = (const float*)d_in[3];
    const float* bk = (const float*)d_in[4];
    const float* Wv = (const float*)d_in[5];
    const float* bv = (const float*)d_in[6];
    float* out = (float*)d_out;

    ushortx *xh, *xl, *wh, *wl, *qh, *ql, *kh, *kl, *vh, *vl;
    cudaGetSymbolAddress((void**)&xh, g_xh);
    cudaGetSymbolAddress((void**)&xl, g_xl);
    cudaGetSymbolAddress((void**)&wh, g_wh);
    cudaGetSymbolAddress((void**)&wl, g_wl);
    cudaGetSymbolAddress((void**)&qh, g_qh);
    cudaGetSymbolAddress((void**)&ql, g_ql);
    cudaGetSymbolAddress((void**)&kh, g_kh);
    cudaGetSymbolAddress((void**)&kl, g_kl);
    cudaGetSymbolAddress((void**)&vh, g_vh);
    cudaGetSymbolAddress((void**)&vl, g_vl);

    // Split fp32 -> bf16 hi/lo
    {
        int n4 = MROWS * DD / 4;
        split_bf16<<<(n4 + 255) / 256, 256>>>(x, xh, xl, n4);
        int w4 = DD * DD / 4;
        split_bf16<<<(w4 + 255) / 256, 256>>>(Wq, wh + 0 * (size_t)DD * DD, wl + 0 * (size_t)DD * DD, w4);
        split_bf16<<<(w4 + 255) / 256, 256>>>(Wk, wh + 1 * (size_t)DD * DD, wl + 1 * (size_t)DD * DD, w4);
        split_bf16<<<(w4 + 255) / 256, 256>>>(Wv, wh + 2 * (size_t)DD * DD, wl + 2 * (size_t)DD * DD, w4);
    }

    GemmArgs ga;
    ga.xh = xh; ga.xl = xl;
    ga.wh[0] = wh;                       ga.wl[0] = wl;
    ga.wh[1] = wh + 1 * (size_t)DD * DD; ga.wl[1] = wl + 1 * (size_t)DD * DD;
    ga.wh[2] = wh + 2 * (size_t)DD * DD; ga.wl[2] = wl + 2 * (size_t)DD * DD;
    ga.bias[0] = bq; ga.bias[1] = bk; ga.bias[2] = bv;
    ga.outh[0] = qh; ga.outl[0] = ql;
    ga.outh[1] = kh; ga.outl[1] = kl;
    ga.outh[2] = vh; ga.outl[2] = vl;

    cudaFuncSetAttribute(qkv_tc_gemm, cudaFuncAttributeMaxDynamicSharedMemorySize,
                         GEMM_DSMEM);
    qkv_tc_gemm<<<dim3(DD / 128, MROWS / 256, 3), 512, GEMM_DSMEM>>>(ga);

    AttnArgs aa;
    aa.qh = qh; aa.ql = ql; aa.kh = kh; aa.kl = kl; aa.vh = vh; aa.vl = vl;
    aa.out = out;
    cudaFuncSetAttribute(attn_tc, cudaFuncAttributeMaxDynamicSharedMemorySize,
                         ATTN_DSMEM);
    attn_tc<<<dim3(NB, BB), 256, ATTN_DSMEM>>>(aa);
}

// round 10
// speedup vs baseline: 4.4595x; 1.4033x over previous
#include <cuda_runtime.h>
#include <cuda_bf16.h>
#include <math.h>
#include <stdint.h>

// Problem constants (fixed shapes)
#define BB 4
#define TT 4096
#define DD 1024
#define SPAN 128
#define NB (TT / SPAN)      // 32
#define MROWS (BB * TT)     // 16384

typedef unsigned short ushortx;

// Scratch (device globals: no allocation APIs allowed)
__device__ float   g_xt[(size_t)MROWS * DD];        // tf32-rounded x
__device__ float   g_wt[(size_t)3 * DD * DD];       // tf32-rounded Wq/Wk/Wv
__device__ ushortx g_qh[(size_t)MROWS * DD];
__device__ ushortx g_ql[(size_t)MROWS * DD];
__device__ ushortx g_kh[(size_t)MROWS * DD];
__device__ ushortx g_kl[(size_t)MROWS * DD];
__device__ ushortx g_vh[(size_t)MROWS * DD];
__device__ ushortx g_vl[(size_t)MROWS * DD];

__device__ __forceinline__ uint32_t smem_u32(const void* p) {
    uint32_t a;
    asm("{ .reg .u64 t; cvta.to.shared.u64 t, %1; cvt.u32.u64 %0, t; }"
        : "=r"(a) : "l"(p));
    return a;
}

#define LDMATRIX_X4(r0, r1, r2, r3, addr) \
    asm volatile("ldmatrix.sync.aligned.m8n8.x4.shared.b16 {%0,%1,%2,%3}, [%4];" \
                 : "=r"(r0), "=r"(r1), "=r"(r2), "=r"(r3) : "r"(addr))
#define LDMATRIX_X4T(r0, r1, r2, r3, addr) \
    asm volatile("ldmatrix.sync.aligned.m8n8.x4.trans.shared.b16 {%0,%1,%2,%3}, [%4];" \
                 : "=r"(r0), "=r"(r1), "=r"(r2), "=r"(r3) : "r"(addr))
#define MMA_16816(c0, c1, c2, c3, a0, a1, a2, a3, b0, b1) \
    asm volatile("mma.sync.aligned.m16n8k16.row.col.f32.bf16.bf16.f32 " \
                 "{%0,%1,%2,%3}, {%4,%5,%6,%7}, {%8,%9}, {%0,%1,%2,%3};" \
                 : "+f"(c0), "+f"(c1), "+f"(c2), "+f"(c3) \
                 : "r"(a0), "r"(a1), "r"(a2), "r"(a3), "r"(b0), "r"(b1))
#define MMA_TF32(c0, c1, c2, c3, a0, a1, a2, a3, b0, b1) \
    asm volatile("mma.sync.aligned.m16n8k8.row.col.f32.tf32.tf32.f32 " \
                 "{%0,%1,%2,%3}, {%4,%5,%6,%7}, {%8,%9}, {%0,%1,%2,%3};" \
                 : "+f"(c0), "+f"(c1), "+f"(c2), "+f"(c3) \
                 : "r"(a0), "r"(a1), "r"(a2), "r"(a3), "r"(b0), "r"(b1))
#define CP_ASYNC_16(dst, src) \
    asm volatile("cp.async.cg.shared.global [%0], [%1], 16;" \
                 :: "r"(dst), "l"(src) : "memory")
#define CP_ASYNC_COMMIT() asm volatile("cp.async.commit_group;" ::: "memory")
#define CP_ASYNC_WAIT(n)  asm volatile("cp.async.wait_group %0;" :: "n"(n) : "memory")

__device__ __forceinline__ void bfsplit(float v, ushortx& h, ushortx& l) {
    __nv_bfloat16 hb = __float2bfloat16(v);
    __nv_bfloat16 lb = __float2bfloat16(v - __bfloat162float(hb));
    h = __bfloat16_as_ushort(hb);
    l = __bfloat16_as_ushort(lb);
}

__device__ __forceinline__ uint32_t to_tf32(float v) {
    uint32_t r;
    asm("cvt.rna.tf32.f32 %0, %1;" : "=r"(r) : "f"(v));
    return r;
}

// ---------------------------------------------------------------------------
// Convert fp32 -> tf32 (round-to-nearest), stored as fp32 bit patterns
// ---------------------------------------------------------------------------
__global__ __launch_bounds__(256) void cvt_tf32(const float* __restrict__ src,
                                                float* __restrict__ dst,
                                                int n4) {
    int i = blockIdx.x * 256 + threadIdx.x;
    if (i >= n4) return;
    float4 v = reinterpret_cast<const float4*>(src)[i];
    uint4 o;
    o.x = to_tf32(v.x); o.y = to_tf32(v.y);
    o.z = to_tf32(v.z); o.w = to_tf32(v.w);
    reinterpret_cast<uint4*>(dst)[i] = o;
}

// ---------------------------------------------------------------------------
// tf32 single-pass tensor-core GEMM:  out = x @ W^T + bias
// CTA tile M=128 x N=128, K-chunk 32 (128B rows fp32), 2-stage cp.async.
// 256 threads = 8 warps (2 m x 4 n), warp tile 64x32, mma m16n8k8 tf32.
// Epilogue emits bf16 hi/lo pairs (attention stage unchanged).
// ---------------------------------------------------------------------------
struct GemmArgs {
    const float* xt;
    const float* wt[3];
    const float* bias[3];
    ushortx* outh[3];
    ushortx* outl[3];
};

#define GC_CHUNKS (DD / 32)        // 32 K-chunks of 32 fp32
#define GT_TILE 16384u             // 128 rows x 128B
#define GT_STAGE 32768u            // A tile + B tile
#define GEMM_DSMEM (2u * GT_STAGE) // 64 KB

__global__ __launch_bounds__(256, 2) void qkv_tc_gemm(GemmArgs args) {
    extern __shared__ char dsm[];
    const int tid = threadIdx.x;
    const int wid = tid >> 5;
    const int lane = tid & 31;
    const int bn = blockIdx.x * 128;
    const int bm = blockIdx.y * 128;
    const int z  = blockIdx.z;
    const int warp_m = wid >> 2;
    const int warp_n = wid & 3;

    const uint32_t smem_base = smem_u32(dsm);

    const float* At = args.xt    + (size_t)bm * DD;
    const float* Bt = args.wt[z] + (size_t)bn * DD;

    auto load_stage = [&](int c, int buf) {
        const int k0 = c * 32;
        const uint32_t sb = smem_base + buf * GT_STAGE;
#pragma unroll
        for (int i = 0; i < 4; ++i) {
            int idx = tid + i * 256;
            int r = idx >> 3, ch = idx & 7;
            uint32_t dst = (uint32_t)(r * 128 + ((ch ^ (r & 7)) * 16));
            const size_t go = (size_t)r * DD + k0 + ch * 4;
            CP_ASYNC_16(sb + dst, At + go);
            CP_ASYNC_16(sb + GT_TILE + dst, Bt + go);
        }
        CP_ASYNC_COMMIT();
    };

    float acc[4][4][4];
#pragma unroll
    for (int mt = 0; mt < 4; ++mt)
#pragma unroll
        for (int nt = 0; nt < 4; ++nt)
#pragma unroll
            for (int j = 0; j < 4; ++j) acc[mt][nt][j] = 0.0f;

    // A (x4 m16k8 tf32): row = warpm*64 + mt*16 + (lane&15), kb = (lane>>4)*16
    const int a_row = warp_m * 64 + (lane & 15);
    const uint32_t a_sw = (uint32_t)((a_row & 7) * 16);
    const uint32_t a_kb = (uint32_t)((lane >> 4) * 16);
    // B (x4, two n8-tiles per load): row = warpn*32 + ntp*16 + (lane&7) + ((lane>>4)<<3)
    const int b_row = warp_n * 32 + (lane & 7) + ((lane >> 4) << 3);
    const uint32_t b_sw = (uint32_t)((lane & 7) * 16);
    const uint32_t b_kb = (uint32_t)(((lane >> 3) & 1) * 16);

    load_stage(0, 0);

    for (int c = 0; c < GC_CHUNKS; ++c) {
        const int buf = c & 1;
        if (c + 1 < GC_CHUNKS) {
            load_stage(c + 1, buf ^ 1);
            CP_ASYNC_WAIT(1);
        } else {
            CP_ASYNC_WAIT(0);
        }
        __syncthreads();

        const uint32_t sb = smem_base + buf * GT_STAGE;
        const uint32_t a_base = sb + a_row * 128;
        const uint32_t b_base = sb + GT_TILE;

#pragma unroll
        for (int ks = 0; ks < 4; ++ks) {
            const uint32_t akb = (uint32_t)(ks * 32) + a_kb;
            uint32_t a[4][4];
#pragma unroll
            for (int mt = 0; mt < 4; ++mt)
                LDMATRIX_X4(a[mt][0], a[mt][1], a[mt][2], a[mt][3],
                            a_base + (uint32_t)(mt * 16 * 128) + (akb ^ a_sw));
#pragma unroll
            for (int ntp = 0; ntp < 2; ++ntp) {
                const uint32_t ba = (uint32_t)((b_row + ntp * 16) * 128) +
                                    (((uint32_t)(ks * 32) + b_kb) ^ b_sw);
                uint32_t b0, b1, b2, b3;
                LDMATRIX_X4(b0, b1, b2, b3, b_base + ba);
                const int n0 = ntp * 2, n1 = ntp * 2 + 1;
#pragma unroll
                for (int mt = 0; mt < 4; ++mt) {
                    MMA_TF32(acc[mt][n0][0], acc[mt][n0][1], acc[mt][n0][2], acc[mt][n0][3],
                             a[mt][0], a[mt][1], a[mt][2], a[mt][3], b0, b1);
                    MMA_TF32(acc[mt][n1][0], acc[mt][n1][1], acc[mt][n1][2], acc[mt][n1][3],
                             a[mt][0], a[mt][1], a[mt][2], a[mt][3], b2, b3);
                }
            }
        }
        __syncthreads();
    }

    // Epilogue: add bias, split to bf16 hi/lo, store
    const float* bias = args.bias[z];
    ushortx* outh = args.outh[z];
    ushortx* outl = args.outl[z];
    const int er = bm + warp_m * 64 + (lane >> 2);
    const int ec = bn + warp_n * 32 + (lane & 3) * 2;
#pragma unroll
    for (int mt = 0; mt < 4; ++mt) {
#pragma unroll
        for (int nt = 0; nt < 4; ++nt) {
            const int r0 = er + mt * 16;
            const int cc = ec + nt * 8;
            float v0 = acc[mt][nt][0] + bias[cc];
            float v1 = acc[mt][nt][1] + bias[cc + 1];
            float v2 = acc[mt][nt][2] + bias[cc];
            float v3 = acc[mt][nt][3] + bias[cc + 1];
            ushort2 h01, l01, h23, l23;
            bfsplit(v0, h01.x, l01.x); bfsplit(v1, h01.y, l01.y);
            bfsplit(v2, h23.x, l23.x); bfsplit(v3, h23.y, l23.y);
            *reinterpret_cast<ushort2*>(outh + (size_t)r0 * DD + cc) = h01;
            *reinterpret_cast<ushort2*>(outl + (size_t)r0 * DD + cc) = l01;
            *reinterpret_cast<ushort2*>(outh + (size_t)(r0 + 8) * DD + cc) = h23;
            *reinterpret_cast<ushort2*>(outl + (size_t)(r0 + 8) * DD + cc) = l23;
        }
    }
}

// ---------------------------------------------------------------------------
// Tensor-core windowed attention (split-bf16, masked-tile skipping; unchanged).
// One CTA per (b, n): 128 q rows x 256 keys. 8 warps (2 m x 4 n).
// ---------------------------------------------------------------------------
struct AttnArgs {
    const ushortx *qh, *ql, *kh, *kl, *vh, *vl;
    float* out;
};

#define NUM_CHUNKS (DD / 64)       // 16 d-chunks for attention phase 1
#define A_STAGE 98304u             // Qh 16K | Ql 16K | Kh 32K | Kl 32K
#define A_QH 0u
#define A_QL 16384u
#define A_KH 32768u
#define A_KL 65536u
#define P_H  0u
#define P_L  65536u
#define V_BASE 131072u
#define ATTN_DSMEM 196608u

__global__ __launch_bounds__(256) void attn_tc(AttnArgs a) {
    extern __shared__ char dsm[];
    __shared__ float redmax[128][4];
    __shared__ float redsum[128][4];

    const int tid = threadIdx.x;
    const int wid = tid >> 5;
    const int lane = tid & 31;
    const int wm = wid >> 2;
    const int wn = wid & 3;
    const int nblk = blockIdx.x;
    const int b = blockIdx.y;
    const size_t qrow0 = (size_t)b * TT + (size_t)nblk * SPAN;
    const int kv0 = (nblk - 1) * SPAN;
    const uint32_t smem = smem_u32(dsm);

    const bool s1skip = ((wn * 64 + 63) <= (wm * 64)) ||
                        ((wn * 64) > (wm * 64 + 191)) ||
                        (nblk == 0 && wn < 2);

    float acc[4][8][4];
#pragma unroll
    for (int mt = 0; mt < 4; ++mt)
#pragma unroll
        for (int nt = 0; nt < 8; ++nt)
#pragma unroll
            for (int j = 0; j < 4; ++j) acc[mt][nt][j] = 0.0f;

    auto load_stage1 = [&](int c, int buf) {
        const int k0 = c * 64;
        const uint32_t sb = smem + buf * A_STAGE;
#pragma unroll
        for (int i = 0; i < 4; ++i) {
            int idx = tid + i * 256;
            int r = idx >> 3, ch = idx & 7;
            uint32_t dst = (uint32_t)(r * 128 + ((ch ^ (r & 7)) * 16));
            const size_t goff = (qrow0 + r) * DD + k0 + ch * 8;
            CP_ASYNC_16(sb + A_QH + dst, a.qh + goff);
            CP_ASYNC_16(sb + A_QL + dst, a.ql + goff);
        }
#pragma unroll
        for (int i = 0; i < 8; ++i) {
            int idx = tid + i * 256;
            int r = idx >> 3, ch = idx & 7;
            int krow = kv0 + r; if (krow < 0) krow = 0;
            uint32_t dst = (uint32_t)(r * 128 + ((ch ^ (r & 7)) * 16));
            const size_t goff = ((size_t)b * TT + krow) * DD + k0 + ch * 8;
            CP_ASYNC_16(sb + A_KH + dst, a.kh + goff);
            CP_ASYNC_16(sb + A_KL + dst, a.kl + goff);
        }
        CP_ASYNC_COMMIT();
    };

    const int a_row = wm * 64 + (lane & 15);
    const uint32_t a_sw = (uint32_t)((a_row & 7) * 16);
    const uint32_t a_kb_lane = (uint32_t)((lane >> 4) * 16);
    const int b_row2 = wn * 64 + (lane & 7) + ((lane >> 4) << 3);
    const uint32_t b_koff = (uint32_t)(((lane >> 3) & 1) * 16);
    const uint32_t b_sw2 = (uint32_t)((lane & 7) * 16);

    load_stage1(0, 0);

    for (int c = 0; c < NUM_CHUNKS; ++c) {
        const int buf = c & 1;
        if (c + 1 < NUM_CHUNKS) {
            load_stage1(c + 1, (c + 1) & 1);
            CP_ASYNC_WAIT(1);
        } else {
            CP_ASYNC_WAIT(0);
        }
        __syncthreads();

        if (!s1skip) {
            const uint32_t sb = smem + buf * A_STAGE;
            const uint32_t a_base_h = sb + A_QH + a_row * 128;
            const uint32_t a_base_l = sb + A_QL + a_row * 128;

#pragma unroll
            for (int ks = 0; ks < 4; ++ks) {
                const uint32_t akb = (uint32_t)(ks * 32) + a_kb_lane;
                uint32_t ah[4][4], al[4][4];
#pragma unroll
                for (int mt = 0; mt < 4; ++mt) {
                    const uint32_t moff = (uint32_t)(mt * 16 * 128);
                    LDMATRIX_X4(ah[mt][0], ah[mt][1], ah[mt][2], ah[mt][3],
                                a_base_h + moff + (akb ^ a_sw));
                    LDMATRIX_X4(al[mt][0], al[mt][1], al[mt][2], al[mt][3],
                                a_base_l + moff + (akb ^ a_sw));
                }
#pragma unroll
                for (int ntp = 0; ntp < 4; ++ntp) {
                    const uint32_t ba = (uint32_t)((b_row2 + ntp * 16) * 128) +
                                        (((uint32_t)(ks * 32) + b_koff) ^ b_sw2);
                    uint32_t bh0, bh1, bh2, bh3, bl0, bl1, bl2, bl3;
                    LDMATRIX_X4(bh0, bh1, bh2, bh3, sb + A_KH + ba);
                    LDMATRIX_X4(bl0, bl1, bl2, bl3, sb + A_KL + ba);
                    const int n0 = ntp * 2, n1 = ntp * 2 + 1;
#pragma unroll
                    for (int mt = 0; mt < 4; ++mt) {
                        MMA_16816(acc[mt][n0][0], acc[mt][n0][1], acc[mt][n0][2], acc[mt][n0][3],
                                  ah[mt][0], ah[mt][1], ah[mt][2], ah[mt][3], bh0, bh1);
                        MMA_16816(acc[mt][n0][0], acc[mt][n0][1], acc[mt][n0][2], acc[mt][n0][3],
                                  ah[mt][0], ah[mt][1], ah[mt][2], ah[mt][3], bl0, bl1);
                        MMA_16816(acc[mt][n0][0], acc[mt][n0][1], acc[mt][n0][2], acc[mt][n0][3],
                                  al[mt][0], al[mt][1], al[mt][2], al[mt][3], bh0, bh1);
                        MMA_16816(acc[mt][n1][0], acc[mt][n1][1], acc[mt][n1][2], acc[mt][n1][3],
                                  ah[mt][0], ah[mt][1], ah[mt][2], ah[mt][3], bh2, bh3);
                        MMA_16816(acc[mt][n1][0], acc[mt][n1][1], acc[mt][n1][2], acc[mt][n1][3],
                                  ah[mt][0], ah[mt][1], ah[mt][2], ah[mt][3], bl2, bl3);
                        MMA_16816(acc[mt][n1][0], acc[mt][n1][1], acc[mt][n1][2], acc[mt][n1][3],
                                  al[mt][0], al[mt][1], al[mt][2], al[mt][3], bh2, bh3);
                    }
                }
            }
        }
        __syncthreads();
    }

    const float scale = 0.03125f;
#pragma unroll
    for (int mt = 0; mt < 4; ++mt) {
#pragma unroll
        for (int half = 0; half < 2; ++half) {
            const int row = wm * 64 + mt * 16 + half * 8 + (lane >> 2);
            float m = -1e30f;
#pragma unroll
            for (int nt = 0; nt < 8; ++nt) {
#pragma unroll
                for (int j = 0; j < 2; ++j) {
                    const int col = wn * 64 + nt * 8 + (lane & 3) * 2 + j;
                    const bool ok = (col > row) && (col <= row + SPAN) &&
                                    (nblk > 0 || col >= SPAN);
                    float s = ok ? acc[mt][nt][half * 2 + j] * scale : -1e30f;
                    acc[mt][nt][half * 2 + j] = s;
                    m = fmaxf(m, s);
                }
            }
            m = fmaxf(m, __shfl_xor_sync(0xFFFFFFFFu, m, 1));
            m = fmaxf(m, __shfl_xor_sync(0xFFFFFFFFu, m, 2));
            if ((lane & 3) == 0) redmax[row][wn] = m;
        }
    }
    __syncthreads();
#pragma unroll
    for (int mt = 0; mt < 4; ++mt) {
#pragma unroll
        for (int half = 0; half < 2; ++half) {
            const int row = wm * 64 + mt * 16 + half * 8 + (lane >> 2);
            float m = fmaxf(fmaxf(redmax[row][0], redmax[row][1]),
                            fmaxf(redmax[row][2], redmax[row][3]));
            float sum = 0.0f;
#pragma unroll
            for (int nt = 0; nt < 8; ++nt) {
#pragma unroll
                for (int j = 0; j < 2; ++j) {
                    float s = acc[mt][nt][half * 2 + j];
                    float p = (s > -1e29f) ? __expf(s - m) : 0.0f;
                    acc[mt][nt][half * 2 + j] = p;
                    sum += p;
                }
            }
            sum += __shfl_xor_sync(0xFFFFFFFFu, sum, 1);
            sum += __shfl_xor_sync(0xFFFFFFFFu, sum, 2);
            if ((lane & 3) == 0) redsum[row][wn] = sum;
        }
    }
    __syncthreads();
#pragma unroll
    for (int mt = 0; mt < 4; ++mt) {
#pragma unroll
        for (int half = 0; half < 2; ++half) {
            const int row = wm * 64 + mt * 16 + half * 8 + (lane >> 2);
            const float inv = 1.0f / (redsum[row][0] + redsum[row][1] +
                                      redsum[row][2] + redsum[row][3]);
#pragma unroll
            for (int nt = 0; nt < 8; ++nt) {
                const int col = wn * 64 + nt * 8 + (lane & 3) * 2;
                float p0 = acc[mt][nt][half * 2 + 0] * inv;
                float p1 = acc[mt][nt][half * 2 + 1] * inv;
                ushort2 h, l;
                bfsplit(p0, h.x, l.x);
                bfsplit(p1, h.y, l.y);
                uint32_t off = (uint32_t)(row * 512 + col * 2);
                off ^= (off >> 5) & 0x70;
                asm volatile("st.shared.b32 [%0], %1;"
                             :: "r"(smem + P_H + off), "r"(*(uint32_t*)&h) : "memory");
                asm volatile("st.shared.b32 [%0], %1;"
                             :: "r"(smem + P_L + off), "r"(*(uint32_t*)&l) : "memory");
            }
        }
    }
    __syncthreads();

    auto load_v = [&](int kc, int buf, int d0) {
        const uint32_t sb = smem + V_BASE + buf * 32768u;
#pragma unroll
        for (int i = 0; i < 4; ++i) {
            int idx = tid + i * 256;
            int r = idx >> 5, ch = idx & 31;
            int vrow = kv0 + kc * 32 + r; if (vrow < 0) vrow = 0;
            uint32_t dst = (uint32_t)(r * 512 + ((ch ^ (r & 7)) * 16));
            const size_t goff = ((size_t)b * TT + vrow) * DD + d0 + ch * 8;
            CP_ASYNC_16(sb + dst, a.vh + goff);
            CP_ASYNC_16(sb + 16384u + dst, a.vl + goff);
        }
        CP_ASYNC_COMMIT();
    };

    for (int dc = 0; dc < 4; ++dc) {
        const int d0 = dc * 256;
        float acc2[4][8][4];
#pragma unroll
        for (int mt = 0; mt < 4; ++mt)
#pragma unroll
            for (int nt = 0; nt < 8; ++nt)
#pragma unroll
                for (int j = 0; j < 4; ++j) acc2[mt][nt][j] = 0.0f;

        load_v(0, 0, d0);
        for (int kc = 0; kc < 8; ++kc) {
            const int buf = kc & 1;
            if (kc + 1 < 8) {
                load_v(kc + 1, (kc + 1) & 1, d0);
                CP_ASYNC_WAIT(1);
            } else {
                CP_ASYNC_WAIT(0);
            }
            __syncthreads();

            const bool pskip = ((kc * 32 + 31) <= (wm * 64)) ||
                               ((kc * 32) > (wm * 64 + 191)) ||
                               (nblk == 0 && kc < 4);
            if (!pskip) {
                const uint32_t vb = smem + V_BASE + buf * 32768u;
#pragma unroll
                for (int ks = 0; ks < 2; ++ks) {
                    const int kbase = kc * 32 + ks * 16;
                    uint32_t ph[4][4], pl[4][4];
#pragma unroll
                    for (int mt = 0; mt < 4; ++mt) {
                        const int prow = wm * 64 + mt * 16 + (lane & 15);
                        uint32_t aoff = (uint32_t)(prow * 512 + kbase * 2 + (lane >> 4) * 16);
                        aoff ^= (aoff >> 5) & 0x70;
                        LDMATRIX_X4(ph[mt][0], ph[mt][1], ph[mt][2], ph[mt][3], smem + P_H + aoff);
                        LDMATRIX_X4(pl[mt][0], pl[mt][1], pl[mt][2], pl[mt][3], smem + P_L + aoff);
                    }
#pragma unroll
                    for (int ntp = 0; ntp < 4; ++ntp) {
                        const int vrow = ks * 16 + (lane & 15);
                        const int vcol = wn * 64 + ntp * 16 + ((lane >> 4) << 3);
                        uint32_t boff = (uint32_t)(vrow * 512 + vcol * 2);
                        boff ^= (boff >> 5) & 0x70;
                        uint32_t vh0, vh1, vh2, vh3, vl0, vl1, vl2, vl3;
                        LDMATRIX_X4T(vh0, vh1, vh2, vh3, vb + boff);
                        LDMATRIX_X4T(vl0, vl1, vl2, vl3, vb + 16384u + boff);
                        const int n0 = ntp * 2, n1 = ntp * 2 + 1;
#pragma unroll
                        for (int mt = 0; mt < 4; ++mt) {
                            MMA_16816(acc2[mt][n0][0], acc2[mt][n0][1], acc2[mt][n0][2], acc2[mt][n0][3],
                                      ph[mt][0], ph[mt][1], ph[mt][2], ph[mt][3], vh0, vh1);
                            MMA_16816(acc2[mt][n0][0], acc2[mt][n0][1], acc2[mt][n0][2], acc2[mt][n0][3],
                                      ph[mt][0], ph[mt][1], ph[mt][2], ph[mt][3], vl0, vl1);
                            MMA_16816(acc2[mt][n0][0], acc2[mt][n0][1], acc2[mt][n0][2], acc2[mt][n0][3],
                                      pl[mt][0], pl[mt][1], pl[mt][2], pl[mt][3], vh0, vh1);
                            MMA_16816(acc2[mt][n1][0], acc2[mt][n1][1], acc2[mt][n1][2], acc2[mt][n1][3],
                                      ph[mt][0], ph[mt][1], ph[mt][2], ph[mt][3], vh2, vh3);
                            MMA_16816(acc2[mt][n1][0], acc2[mt][n1][1], acc2[mt][n1][2], acc2[mt][n1][3],
                                      ph[mt][0], ph[mt][1], ph[mt][2], ph[mt][3], vl2, vl3);
                            MMA_16816(acc2[mt][n1][0], acc2[mt][n1][1], acc2[mt][n1][2], acc2[mt][n1][3],
                                      pl[mt][0], pl[mt][1], pl[mt][2], pl[mt][3], vh2, vh3);
                        }
                    }
                }
            }
            __syncthreads();
        }

#pragma unroll
        for (int mt = 0; mt < 4; ++mt) {
#pragma unroll
            for (int nt = 0; nt < 8; ++nt) {
                const size_t row = qrow0 + wm * 64 + mt * 16 + (lane >> 2);
                const int col = d0 + wn * 64 + nt * 8 + (lane & 3) * 2;
                float2 v0 = make_float2(acc2[mt][nt][0], acc2[mt][nt][1]);
                float2 v1 = make_float2(acc2[mt][nt][2], acc2[mt][nt][3]);
                *reinterpret_cast<float2*>(a.out + row * DD + col) = v0;
                *reinterpret_cast<float2*>(a.out + (row + 8) * DD + col) = v1;
            }
        }
    }
}

// ---------------------------------------------------------------------------
extern "C" void kernel_launch(void* const* d_in, const int* in_sizes, int n_in,
                              void* d_out, int out_size) {
    const float* x  = (const float*)d_in[0];
    const float* Wq = (const float*)d_in[1];
    const float* bq = (const float*)d_in[2];
    const float* Wk = (const float*)d_in[3];
    const float* bk = (const float*)d_in[4];
    const float* Wv = (const float*)d_in[5];
    const float* bv = (const float*)d_in[6];
    float* out = (float*)d_out;

    float *xt, *wt;
    ushortx *qh, *ql, *kh, *kl, *vh, *vl;
    cudaGetSymbolAddress((void**)&xt, g_xt);
    cudaGetSymbolAddress((void**)&wt, g_wt);
    cudaGetSymbolAddress((void**)&qh, g_qh);
    cudaGetSymbolAddress((void**)&ql, g_ql);
    cudaGetSymbolAddress((void**)&kh, g_kh);
    cudaGetSymbolAddress((void**)&kl, g_kl);
    cudaGetSymbolAddress((void**)&vh, g_vh);
    cudaGetSymbolAddress((void**)&vl, g_vl);

    // Convert fp32 -> tf32
    {
        int n4 = MROWS * DD / 4;
        cvt_tf32<<<(n4 + 255) / 256, 256>>>(x, xt, n4);
        int w4 = DD * DD / 4;
        cvt_tf32<<<(w4 + 255) / 256, 256>>>(Wq, wt + 0 * (size_t)DD * DD, w4);
        cvt_tf32<<<(w4 + 255) / 256, 256>>>(Wk, wt + 1 * (size_t)DD * DD, w4);
        cvt_tf32<<<(w4 + 255) / 256, 256>>>(Wv, wt + 2 * (size_t)DD * DD, w4);
    }

    GemmArgs ga;
    ga.xt = xt;
    ga.wt[0] = wt;
    ga.wt[1] = wt + 1 * (size_t)DD * DD;
    ga.wt[2] = wt + 2 * (size_t)DD * DD;
    ga.bias[0] = bq; ga.bias[1] = bk; ga.bias[2] = bv;
    ga.outh[0] = qh; ga.outl[0] = ql;
    ga.outh[1] = kh; ga.outl[1] = kl;
    ga.outh[2] = vh; ga.outl[2] = vl;

    cudaFuncSetAttribute(qkv_tc_gemm, cudaFuncAttributeMaxDynamicSharedMemorySize,
                         GEMM_DSMEM);
    qkv_tc_gemm<<<dim3(DD / 128, MROWS / 128, 3), 256, GEMM_DSMEM>>>(ga);

    AttnArgs aa;
    aa.qh = qh; aa.ql = ql; aa.kh = kh; aa.kl = kl; aa.vh = vh; aa.vl = vl;
    aa.out = out;
    cudaFuncSetAttribute(attn_tc, cudaFuncAttributeMaxDynamicSharedMemorySize,
                         ATTN_DSMEM);
    attn_tc<<<dim3(NB, BB), 256, ATTN_DSMEM>>>(aa);
}